// round 7
// baseline (speedup 1.0000x reference)
#include <cuda_runtime.h>
#include <cuda_fp16.h>
#include <math.h>
#include <stdint.h>

#define Bk 8
#define Nn 8192
#define Ee 16384
#define Dd 128
#define Mm 20
#define Ll 3
#define Rr 200

// ---- edge kernel geometry ----
#define CH 32                    // k-chunk
#define ESTR 40                  // smem row stride (halves)
#define TILE_H (128*ESTR)
#define STAGE_H (4*TILE_H)       // AHI, ALO, BHI, BLO
#define NSTG 4
#define ESMEM (NSTG*STAGE_H*2)   // 163840 bytes

// ---- update kernel geometry (validated) ----
#define USTR 72
#define USMEM ((size_t)(4*128*USTR)*2)

// -------- device scratch --------
__device__ float g_h[(size_t)Bk*Nn*Dd];
__device__ float g_de[(size_t)Bk*Nn*Dd];
__device__ float g_aggr[(size_t)Bk*Nn*Dd];
__device__ float g_scores[Bk*Nn];
__device__ __half g_hhi[(size_t)Bk*Nn*Dd],  g_hlo[(size_t)Bk*Nn*Dd];
__device__ __half g_dehi[(size_t)Bk*Nn*Dd], g_delo[(size_t)Bk*Nn*Dd];
__device__ __half g_confhi[(size_t)Bk*Ee*Dd], g_conflo[(size_t)Bk*Ee*Dd];
__device__ __half g_relhi[Rr*Dd], g_rello[Rr*Dd];
__device__ __half g_msgWhi[(size_t)Ll*20*128*32], g_msgWlo[(size_t)Ll*20*128*32];
__device__ __half g_updWhi[(size_t)Ll*2*128*64],  g_updWlo[(size_t)Ll*2*128*64];

__device__ __forceinline__ uint32_t smem_u32(const void* p){
    uint32_t a;
    asm("{ .reg .u64 t; cvta.to.shared.u64 t, %1; cvt.u32.u64 %0, t; }" : "=r"(a) : "l"(p));
    return a;
}
__device__ __forceinline__ void cpa16(uint32_t dst, const void* src){
    asm volatile("cp.async.cg.shared.global [%0], [%1], 16;" :: "r"(dst), "l"(src));
}
#define CP_COMMIT() asm volatile("cp.async.commit_group;" ::: "memory")

#define LDSM4(r, addr) \
    asm volatile("ldmatrix.sync.aligned.m8n8.x4.shared.b16 {%0,%1,%2,%3}, [%4];" \
        : "=r"((r)[0]), "=r"((r)[1]), "=r"((r)[2]), "=r"((r)[3]) : "r"(addr))

#define MMA_F16(c, a, b0, b1) \
    asm volatile("mma.sync.aligned.m16n8k16.row.col.f32.f16.f16.f32 " \
        "{%0,%1,%2,%3}, {%4,%5,%6,%7}, {%8,%9}, {%0,%1,%2,%3};" \
        : "+f"((c)[0]), "+f"((c)[1]), "+f"((c)[2]), "+f"((c)[3]) \
        : "r"((a)[0]), "r"((a)[1]), "r"((a)[2]), "r"((a)[3]), "r"(b0), "r"(b1))

// ---------------- prep: dist_emb + h init (+ fp16 splits) ----------------
__global__ void prep_kernel(const int* __restrict__ dists,
                            const float* __restrict__ noise,
                            const float* __restrict__ dtab)
{
    int i = blockIdx.x * blockDim.x + threadIdx.x;
    if (i >= Bk*Nn*Dd/4) return;
    int node = i >> 5;
    int c = i & 31;
    int di = dists[node];
    di = di < 0 ? 0 : (di > 9 ? 9 : di);
    float4 dv = __ldg(((const float4*)(dtab + (size_t)di*Dd)) + c);
    float4 nz = ((const float4*)noise)[i];
    float4 h;
    h.x = dv.x + 0.1f*nz.x; h.y = dv.y + 0.1f*nz.y;
    h.z = dv.z + 0.1f*nz.z; h.w = dv.w + 0.1f*nz.w;
    ((float4*)g_de)[i] = dv;
    ((float4*)g_h)[i]  = h;

    __half2* p;
    __half a0, a1;
    a0 = __float2half_rn(h.x); a1 = __float2half_rn(h.y);
    p = (__half2*)g_hhi; p[2*i] = __halves2half2(a0, a1);
    p = (__half2*)g_hlo; p[2*i] = __halves2half2(__float2half_rn(h.x-__half2float(a0)), __float2half_rn(h.y-__half2float(a1)));
    a0 = __float2half_rn(h.z); a1 = __float2half_rn(h.w);
    p = (__half2*)g_hhi; p[2*i+1] = __halves2half2(a0, a1);
    p = (__half2*)g_hlo; p[2*i+1] = __halves2half2(__float2half_rn(h.z-__half2float(a0)), __float2half_rn(h.w-__half2float(a1)));
    a0 = __float2half_rn(dv.x); a1 = __float2half_rn(dv.y);
    p = (__half2*)g_dehi; p[2*i] = __halves2half2(a0, a1);
    p = (__half2*)g_delo; p[2*i] = __halves2half2(__float2half_rn(dv.x-__half2float(a0)), __float2half_rn(dv.y-__half2float(a1)));
    a0 = __float2half_rn(dv.z); a1 = __float2half_rn(dv.w);
    p = (__half2*)g_dehi; p[2*i+1] = __halves2half2(a0, a1);
    p = (__half2*)g_delo; p[2*i+1] = __halves2half2(__float2half_rn(dv.z-__half2float(a0)), __float2half_rn(dv.w-__half2float(a1)));
}

// ---------------- prep: conf + rel_table fp16 splits ----------------
__global__ void prep_aux(const float* __restrict__ conf, const float* __restrict__ rel_table)
{
    int i = blockIdx.x * blockDim.x + threadIdx.x;
    const int CT = Bk*Ee*Dd/4;
    float4 v; __half* hi; __half* lo; int base;
    if (i < CT) { v = ((const float4*)conf)[i]; hi = g_confhi; lo = g_conflo; base = i*4; }
    else {
        int j = i - CT;
        if (j >= Rr*Dd/4) return;
        v = ((const float4*)rel_table)[j]; hi = g_relhi; lo = g_rello; base = j*4;
    }
    __half a0 = __float2half_rn(v.x), a1 = __float2half_rn(v.y);
    __half a2 = __float2half_rn(v.z), a3 = __float2half_rn(v.w);
    *(__half2*)(hi + base)     = __halves2half2(a0, a1);
    *(__half2*)(hi + base + 2) = __halves2half2(a2, a3);
    *(__half2*)(lo + base)     = __halves2half2(__float2half_rn(v.x-__half2float(a0)), __float2half_rn(v.y-__half2float(a1)));
    *(__half2*)(lo + base + 2) = __halves2half2(__float2half_rn(v.z-__half2float(a2)), __float2half_rn(v.w-__half2float(a3)));
}

// ---------------- weight prep ----------------
__global__ void prep_weights(const float* __restrict__ msgW, const float* __restrict__ updW)
{
    int i = blockIdx.x * blockDim.x + threadIdx.x;
    const int MSGTOT = Ll*5*Dd*Dd;
    if (i < MSGTOT) {
        int l = i / (640*128);
        int k = (i / 128) % 640;
        int n = i & 127;
        int ch = k >> 5, kk = k & 31;
        float w = msgW[i];
        __half hi = __float2half_rn(w);
        __half lo = __float2half_rn(w - __half2float(hi));
        size_t o = (((size_t)(l*20 + ch))*128 + n)*32 + kk;
        g_msgWhi[o] = hi; g_msgWlo[o] = lo;
    } else {
        int j = i - MSGTOT;
        if (j < Ll*Dd*Dd) {
            int l = j / (128*128);
            int k = (j / 128) % 128;
            int n = j & 127;
            int ch = k >> 6, kk = k & 63;
            float w = updW[j];
            __half hi = __float2half_rn(w);
            __half lo = __float2half_rn(w - __half2float(hi));
            size_t o = (((size_t)(l*2 + ch))*128 + n)*64 + kk;
            g_updWhi[o] = hi; g_updWlo[o] = lo;
        }
    }
}

// ---------------- edge GEMM: 512 thr, 4-stage cp.async ring, ldmatrix, fp16-split ----------------
// CTA: 128 edges x 128 out, K=640 as 20 k32-chunks. 16 warps 4(M)x4(N), warp tile 32x32.
__global__ void __launch_bounds__(512, 1)
edge_hmma_kernel(int layer,
                 const int* __restrict__ edge_index,
                 const int* __restrict__ rels,
                 const int* __restrict__ edge_mask,
                 const float* __restrict__ rel_table,
                 const float* __restrict__ bias)
{
    extern __shared__ __half sm[];
    __shared__ int   s_src[128], s_tgt[128], s_rel[128];
    __shared__ float s_em[128], s_bias[128];

    int tid = threadIdx.x, wid = tid >> 5, lane = tid & 31;
    int b  = blockIdx.x >> 7;
    int e0 = (blockIdx.x & 127) << 7;

    if (tid < 128) {
        int e = e0 + tid;
        s_src[tid] = edge_index[(size_t)b*2*Ee + e];
        s_tgt[tid] = edge_index[(size_t)b*2*Ee + Ee + e];
        s_rel[tid] = rels[(size_t)b*Ee + e];
        s_em[tid]  = edge_mask[(size_t)b*Ee + e] ? 1.f : 0.f;
        s_bias[tid] = bias[tid];
    }
    __syncthreads();

    uint32_t smb = smem_u32(sm);
    size_t bN = (size_t)b * Nn;
    int wm = wid & 3, wn = wid >> 2;
    int g = lane >> 2, t4 = lane & 3;

    float acc[2][4][4];
    #pragma unroll
    for (int i = 0; i < 2; i++)
        #pragma unroll
        for (int j = 0; j < 4; j++)
            #pragma unroll
            for (int q = 0; q < 4; q++) acc[i][j][q] = 0.f;

    // per-thread fixed gather slot: one 16B quarter of one row
    int ge = tid >> 2, gq = tid & 3;            // edge/n-row 0..127, quarter 0..3
    uint32_t doff = (uint32_t)(ge*ESTR + gq*8)*2;

    auto issue = [&](int c, int st){
        uint32_t sb = smb + (uint32_t)(st*STAGE_H)*2;
        int wc = (c < 16) ? c + 4 : c - 16;
        const __half* wh = g_msgWhi + ((size_t)(layer*20 + wc))*4096;
        const __half* wl = g_msgWlo + ((size_t)(layer*20 + wc))*4096;
        uint32_t dB = sb + (uint32_t)(2*TILE_H)*2 + doff;
        cpa16(dB,            wh + ge*32 + gq*8);
        cpa16(dB + TILE_H*2, wl + ge*32 + gq*8);
        if (c < 16){
            int sg = c >> 2;
            int koff = (c & 3)*CH;
            size_t rowoff;
            const __half *ph, *pl;
            if (sg == 0)      { rowoff = (bN + s_src[ge])*Dd; ph = g_hhi;   pl = g_hlo; }
            else if (sg == 1) { rowoff = (bN + s_src[ge])*Dd; ph = g_dehi;  pl = g_delo; }
            else if (sg == 2) { rowoff = (size_t)s_rel[ge]*Dd; ph = g_relhi; pl = g_rello; }
            else              { rowoff = ((size_t)b*Ee + e0 + ge)*Dd; ph = g_confhi; pl = g_conflo; }
            uint32_t dA = sb + doff;
            cpa16(dA,            ph + rowoff + koff + gq*8);
            cpa16(dA + TILE_H*2, pl + rowoff + koff + gq*8);
        }
    };
    auto fill0 = [&](int c, int st){
        __half* base = sm + st*STAGE_H;
        int koff = (c - 16)*CH;
        const float* hp = g_h + (bN + s_src[ge])*Dd + koff + gq*8;
        const float* rp = rel_table + (size_t)s_rel[ge]*Dd + koff + gq*8;
        float4 h1 = *(const float4*)hp, h2 = *(const float4*)(hp + 4);
        float4 r1 = *(const float4*)rp, r2 = *(const float4*)(rp + 4);
        float pr[8] = {h1.x*r1.x, h1.y*r1.y, h1.z*r1.z, h1.w*r1.w,
                       h2.x*r2.x, h2.y*r2.y, h2.z*r2.z, h2.w*r2.w};
        __half hh[8], ll[8];
        #pragma unroll
        for (int u = 0; u < 8; u++){
            hh[u] = __float2half_rn(pr[u]);
            ll[u] = __float2half_rn(pr[u] - __half2float(hh[u]));
        }
        *(uint4*)(base + ge*ESTR + gq*8)          = *(uint4*)hh;
        *(uint4*)(base + TILE_H + ge*ESTR + gq*8) = *(uint4*)ll;
    };

    // preload stages 0..2 (chunks 0..2, all pure-copy segs)
    issue(0, 0); CP_COMMIT();
    issue(1, 1); CP_COMMIT();
    issue(2, 2); CP_COMMIT();

    for (int c = 0; c < 20; c++){
        int st = c & (NSTG-1);
        // prefetch chunk c+3 into stage (c+3)%4 (freed: its last consumer was chunk c-1)
        if (c + 3 < 20){
            int nst = (c + 3) & (NSTG-1);
            issue(c + 3, nst);
            if (c + 3 >= 16) fill0(c + 3, nst);
        }
        CP_COMMIT();                                   // empty group when no issue — keeps count uniform
        asm volatile("cp.async.wait_group 3;" ::: "memory");
        __syncthreads();

        uint32_t sb = smb + (uint32_t)(st*STAGE_H)*2;
        #pragma unroll
        for (int k16 = 0; k16 < 2; k16++){
            int kb = k16*16;
            uint32_t ah[2][4], al[2][4];
            #pragma unroll
            for (int i = 0; i < 2; i++){
                uint32_t a = sb + (uint32_t)((wm*32 + i*16 + (lane & 15))*ESTR + kb + (lane >> 4)*8)*2;
                LDSM4(ah[i], a);
                LDSM4(al[i], a + TILE_H*2);
            }
            #pragma unroll
            for (int jp = 0; jp < 2; jp++){
                uint32_t bb = sb + (uint32_t)(2*TILE_H + (wn*32 + jp*16 + (lane & 15))*ESTR + kb + (lane >> 4)*8)*2;
                uint32_t bh[4], bl[4];
                LDSM4(bh, bb);
                LDSM4(bl, bb + TILE_H*2);
                #pragma unroll
                for (int i = 0; i < 2; i++){
                    MMA_F16(acc[i][jp*2+0], ah[i], bh[0], bh[2]);
                    MMA_F16(acc[i][jp*2+1], ah[i], bh[1], bh[3]);
                    MMA_F16(acc[i][jp*2+0], ah[i], bl[0], bl[2]);
                    MMA_F16(acc[i][jp*2+1], ah[i], bl[1], bl[3]);
                    MMA_F16(acc[i][jp*2+0], al[i], bh[0], bh[2]);
                    MMA_F16(acc[i][jp*2+1], al[i], bh[1], bh[3]);
                }
            }
        }
        __syncthreads();          // stage free for reuse
    }

    // epilogue: relu + bias + mask, scatter-add (warp tile 32x32)
    #pragma unroll
    for (int i = 0; i < 2; i++) {
        #pragma unroll
        for (int half = 0; half < 2; half++) {
            int row = wm*32 + i*16 + g + half*8;
            if (s_em[row] != 0.f) {
                float* dst = g_aggr + (bN + s_tgt[row])*Dd;
                #pragma unroll
                for (int j = 0; j < 4; j++) {
                    int col = wn*32 + j*8 + t4*2;
                    float v0 = acc[i][j][half*2+0] + s_bias[col];
                    float v1 = acc[i][j][half*2+1] + s_bias[col+1];
                    if (v0 > 0.f) atomicAdd(dst + col,     v0);
                    if (v1 > 0.f) atomicAdd(dst + col + 1, v1);
                }
            }
        }
    }
}

// ---------------- node update GEMM (validated) + fused h re-split ----------------
__global__ void __launch_bounds__(256, 2)
update_hmma_kernel(int layer, const float* __restrict__ bias)
{
    extern __shared__ __half sm[];
    __half* sAhi = sm;
    __half* sAlo = sAhi + 128*USTR;
    __half* sBhi = sAlo + 128*USTR;
    __half* sBlo = sBhi + 128*USTR;
    __shared__ float s_bias[128];

    int tid = threadIdx.x, wid = tid >> 5, lane = tid & 31;
    size_t r0 = (size_t)blockIdx.x * 128;
    if (tid < 128) s_bias[tid] = bias[tid];
    __syncthreads();

    int wm = wid & 3, wn = wid >> 2;
    int g = lane >> 2, t4 = lane & 3;

    float acc[2][8][4];
    #pragma unroll
    for (int i = 0; i < 2; i++)
        #pragma unroll
        for (int j = 0; j < 8; j++)
            #pragma unroll
            for (int q = 0; q < 4; q++) acc[i][j][q] = 0.f;

    for (int c = 0; c < 2; c++) {
        int koff = c*64;
        #pragma unroll
        for (int it = 0; it < 8; it++) {
            int idx = tid + it*256;
            int row = idx >> 4, q = idx & 15;
            float4 v = *(const float4*)(g_aggr + (r0 + row)*Dd + koff + q*4);
            __half h0 = __float2half_rn(v.x), h1 = __float2half_rn(v.y);
            __half h2 = __float2half_rn(v.z), h3 = __float2half_rn(v.w);
            int ho = row*USTR + q*4;
            *(__half2*)(sAhi + ho)     = __halves2half2(h0, h1);
            *(__half2*)(sAhi + ho + 2) = __halves2half2(h2, h3);
            *(__half2*)(sAlo + ho)     = __halves2half2(__float2half_rn(v.x-__half2float(h0)), __float2half_rn(v.y-__half2float(h1)));
            *(__half2*)(sAlo + ho + 2) = __halves2half2(__float2half_rn(v.z-__half2float(h2)), __float2half_rn(v.w-__half2float(h3)));
        }
        {
            const uint4* wh = (const uint4*)(g_updWhi + ((size_t)(layer*2 + c))*8192);
            const uint4* wl = (const uint4*)(g_updWlo + ((size_t)(layer*2 + c))*8192);
            #pragma unroll
            for (int it = 0; it < 4; it++) {
                int idx = tid + it*256;
                int n = idx >> 3, q = idx & 7;
                *(uint4*)(sBhi + n*USTR + q*8) = __ldg(wh + idx);
                *(uint4*)(sBlo + n*USTR + q*8) = __ldg(wl + idx);
            }
        }
        __syncthreads();

        #pragma unroll
        for (int k16 = 0; k16 < 4; k16++) {
            int kb = k16*16;
            uint32_t ahi[2][4], alo[2][4];
            #pragma unroll
            for (int i = 0; i < 2; i++) {
                uint32_t a = smem_u32(sAhi + (wm*32 + i*16 + (lane & 15))*USTR + kb + (lane >> 4)*8);
                LDSM4(ahi[i], a);
                LDSM4(alo[i], a + 128*USTR*2);
            }
            #pragma unroll
            for (int jp = 0; jp < 4; jp++) {
                uint32_t bb = smem_u32(sBhi + (wn*64 + jp*16 + (lane & 15))*USTR + kb + (lane >> 4)*8);
                uint32_t bh[4], bl[4];
                LDSM4(bh, bb);
                LDSM4(bl, bb + 128*USTR*2);
                #pragma unroll
                for (int i = 0; i < 2; i++) {
                    MMA_F16(acc[i][jp*2+0], ahi[i], bh[0], bh[2]);
                    MMA_F16(acc[i][jp*2+1], ahi[i], bh[1], bh[3]);
                    MMA_F16(acc[i][jp*2+0], ahi[i], bl[0], bl[2]);
                    MMA_F16(acc[i][jp*2+1], ahi[i], bl[1], bl[3]);
                    MMA_F16(acc[i][jp*2+0], alo[i], bh[0], bh[2]);
                    MMA_F16(acc[i][jp*2+1], alo[i], bh[1], bh[3]);
                }
            }
        }
        __syncthreads();
    }

    #pragma unroll
    for (int i = 0; i < 2; i++) {
        #pragma unroll
        for (int half = 0; half < 2; half++) {
            int row = wm*32 + i*16 + g + half*8;
            size_t gro = (r0 + row)*Dd;
            float* hp = g_h + gro;
            #pragma unroll
            for (int j = 0; j < 8; j++) {
                int col = wn*64 + j*8 + t4*2;
                float v0 = hp[col]     + acc[i][j][half*2+0] + s_bias[col];
                float v1 = hp[col + 1] + acc[i][j][half*2+1] + s_bias[col+1];
                hp[col] = v0; hp[col + 1] = v1;
                __half a0 = __float2half_rn(v0), a1 = __float2half_rn(v1);
                *(__half2*)(g_hhi + gro + col) = __halves2half2(a0, a1);
                *(__half2*)(g_hlo + gro + col) = __halves2half2(
                    __float2half_rn(v0 - __half2float(a0)),
                    __float2half_rn(v1 - __half2float(a1)));
            }
        }
    }
}

// ---------------- attention scores ----------------
__global__ void score_kernel(const float* __restrict__ attW, const float* __restrict__ attb,
                             const int* __restrict__ node_mask,
                             const float* __restrict__ rq)
{
    int gw = blockIdx.x*8 + (threadIdx.x >> 5);
    int lane = threadIdx.x & 31;
    int b = gw / Nn, n = gw % Nn;
    const float* hrow = g_h + (size_t)gw*Dd;
    float s = 0.f;
    #pragma unroll
    for (int i = 0; i < 4; i++) {
        int d = lane + i*32;
        s = fmaf(hrow[d], attW[d], s);
        s = fmaf(rq[b*Dd + d], attW[Dd + d], s);
    }
    #pragma unroll
    for (int o = 16; o; o >>= 1) s += __shfl_xor_sync(0xffffffffu, s, o);
    if (lane == 0) {
        s += attb[0];
        s = (s > 0.f) ? s : 0.01f * s;
        if (!node_mask[(size_t)b*Nn + n]) s = -1e9f;
        g_scores[gw] = s;
    }
}

// ---------------- softmax + top-20 + output (1 block / batch) ----------------
__global__ void __launch_bounds__(1024)
topk_kernel(const int* __restrict__ node_mask, float* __restrict__ out)
{
    __shared__ float ss[Nn];
    __shared__ float rv[1024];
    __shared__ int   ri[1024];
    __shared__ float s_max, s_sum;
    __shared__ int   top_i[Mm];
    __shared__ float top_v[Mm];

    int b = blockIdx.x;
    int t = threadIdx.x;

    for (int i = t; i < Nn; i += 1024) ss[i] = g_scores[(size_t)b*Nn + i];
    __syncthreads();

    float m = -INFINITY;
    for (int i = t; i < Nn; i += 1024) m = fmaxf(m, ss[i]);
    rv[t] = m; __syncthreads();
    for (int s = 512; s > 0; s >>= 1) { if (t < s) rv[t] = fmaxf(rv[t], rv[t+s]); __syncthreads(); }
    if (t == 0) s_max = rv[0];
    __syncthreads();
    float vmax = s_max;

    float sum = 0.f;
    for (int i = t; i < Nn; i += 1024) sum += expf(ss[i] - vmax);
    rv[t] = sum; __syncthreads();
    for (int s = 512; s > 0; s >>= 1) { if (t < s) rv[t] += rv[t+s]; __syncthreads(); }
    if (t == 0) s_sum = rv[0];
    __syncthreads();
    float inv = 1.f / s_sum;

    for (int sel = 0; sel < Mm; sel++) {
        float bv = -INFINITY; int bi = Nn;
        for (int i = t; i < Nn; i += 1024) {
            float v = ss[i];
            if (v > bv) { bv = v; bi = i; }
        }
        rv[t] = bv; ri[t] = bi; __syncthreads();
        for (int s = 512; s > 0; s >>= 1) {
            if (t < s) {
                if (rv[t+s] > rv[t] || (rv[t+s] == rv[t] && ri[t+s] < ri[t])) {
                    rv[t] = rv[t+s]; ri[t] = ri[t+s];
                }
            }
            __syncthreads();
        }
        if (t == 0) { top_i[sel] = ri[0]; top_v[sel] = rv[0]; ss[ri[0]] = -INFINITY; }
        __syncthreads();
    }

    for (int i = t; i < Mm*Dd; i += 1024) {
        int sel = i / Dd, d = i % Dd;
        int idx = top_i[sel];
        float alpha = expf(top_v[sel] - vmax) * inv;
        float mk = node_mask[(size_t)b*Nn + idx] ? 1.f : 0.f;
        float hv = g_h[((size_t)b*Nn + idx)*Dd + d] * mk;
        out[((size_t)b*Mm + sel)*Dd + d] = hv * alpha;
    }
    float m0 = node_mask[(size_t)b*Nn] ? 1.f : 0.f;
    for (int d = t; d < Dd; d += 1024)
        out[(size_t)Bk*Mm*Dd + (size_t)b*Dd + d] = g_h[((size_t)b*Nn)*Dd + d] * m0;
}

// ---------------- launch ----------------
extern "C" void kernel_launch(void* const* d_in, const int* in_sizes, int n_in,
                              void* d_out, int out_size)
{
    (void)in_sizes; (void)n_in; (void)out_size;
    const int*   dists      = (const int*)d_in[0];
    const int*   edge_index = (const int*)d_in[1];
    const int*   rels       = (const int*)d_in[2];
    const int*   node_mask  = (const int*)d_in[3];
    const int*   edge_mask  = (const int*)d_in[4];
    const float* rq         = (const float*)d_in[5];
    const float* conf       = (const float*)d_in[6];
    const float* noise      = (const float*)d_in[7];
    const float* dist_table = (const float*)d_in[8];
    const float* rel_table  = (const float*)d_in[9];
    const float* msg_W      = (const float*)d_in[10];
    const float* msg_b      = (const float*)d_in[11];
    const float* upd_W      = (const float*)d_in[12];
    const float* upd_b      = (const float*)d_in[13];
    const float* att_W      = (const float*)d_in[14];
    const float* att_b      = (const float*)d_in[15];
    float* out = (float*)d_out;

    cudaFuncSetAttribute(edge_hmma_kernel, cudaFuncAttributeMaxDynamicSharedMemorySize, ESMEM);
    cudaFuncSetAttribute(update_hmma_kernel, cudaFuncAttributeMaxDynamicSharedMemorySize, (int)USMEM);
    void* aggr_ptr = nullptr;
    cudaGetSymbolAddress(&aggr_ptr, g_aggr);

    int total4 = Bk*Nn*Dd/4;
    prep_kernel<<<(total4 + 255)/256, 256>>>(dists, noise, dist_table);
    prep_aux<<<(Bk*Ee*Dd/4 + Rr*Dd/4 + 255)/256, 256>>>(conf, rel_table);
    prep_weights<<<(Ll*5*Dd*Dd + Ll*Dd*Dd + 255)/256, 256>>>(msg_W, upd_W);

    for (int l = 0; l < Ll; l++) {
        cudaMemsetAsync(aggr_ptr, 0, sizeof(float)*(size_t)Bk*Nn*Dd);
        edge_hmma_kernel<<<Bk*(Ee/128), 512, ESMEM>>>(
            l, edge_index, rels, edge_mask, rel_table, msg_b + (size_t)l*Dd);
        update_hmma_kernel<<<Bk*Nn/128, 256, USMEM>>>(l, upd_b + (size_t)l*Dd);
    }

    score_kernel<<<Bk*Nn/8, 256>>>(att_W, att_b, node_mask, rq);
    topk_kernel<<<Bk, 1024>>>(node_mask, out);
}

// round 8
// speedup vs baseline: 1.0156x; 1.0156x over previous
#include <cuda_runtime.h>
#include <cuda_fp16.h>
#include <math.h>
#include <stdint.h>

#define Bk 8
#define Nn 8192
#define Ee 16384
#define Dd 128
#define Mm 20
#define Ll 3
#define Rr 200

// ---- edge kernel geometry (R6 validated) ----
#define CH 32
#define ESTR 40
#define TILE_H (128*ESTR)
#define STAGE_H (4*TILE_H)
#define ESMEM (2*STAGE_H*2)      // 81920 bytes, 2 stages

// ---- update kernel geometry (validated) ----
#define USTR 72
#define USMEM ((size_t)(4*128*USTR)*2)

// -------- device scratch --------
__device__ float g_h[(size_t)Bk*Nn*Dd];
__device__ float g_de[(size_t)Bk*Nn*Dd];
__device__ float g_aggr[(size_t)Bk*Nn*Dd];
__device__ float g_scores[Bk*Nn];
__device__ __half g_hhi[(size_t)Bk*Nn*Dd],  g_hlo[(size_t)Bk*Nn*Dd];
__device__ __half g_dehi[(size_t)Bk*Nn*Dd], g_delo[(size_t)Bk*Nn*Dd];
__device__ __half g_confhi[(size_t)Bk*Ee*Dd], g_conflo[(size_t)Bk*Ee*Dd];
__device__ __half g_relhi[Rr*Dd], g_rello[Rr*Dd];
__device__ __half g_msgWhi[(size_t)Ll*20*128*32], g_msgWlo[(size_t)Ll*20*128*32];
__device__ __half g_updWhi[(size_t)Ll*2*128*64],  g_updWlo[(size_t)Ll*2*128*64];

__device__ __forceinline__ uint32_t smem_u32(const void* p){
    uint32_t a;
    asm("{ .reg .u64 t; cvta.to.shared.u64 t, %1; cvt.u32.u64 %0, t; }" : "=r"(a) : "l"(p));
    return a;
}
__device__ __forceinline__ void cpa16(uint32_t dst, const void* src){
    asm volatile("cp.async.cg.shared.global [%0], [%1], 16;" :: "r"(dst), "l"(src));
}
#define CP_COMMIT() asm volatile("cp.async.commit_group;" ::: "memory")

#define LDSM4(r, addr) \
    asm volatile("ldmatrix.sync.aligned.m8n8.x4.shared.b16 {%0,%1,%2,%3}, [%4];" \
        : "=r"((r)[0]), "=r"((r)[1]), "=r"((r)[2]), "=r"((r)[3]) : "r"(addr))

#define MMA_F16(c, a, b0, b1) \
    asm volatile("mma.sync.aligned.m16n8k16.row.col.f32.f16.f16.f32 " \
        "{%0,%1,%2,%3}, {%4,%5,%6,%7}, {%8,%9}, {%0,%1,%2,%3};" \
        : "+f"((c)[0]), "+f"((c)[1]), "+f"((c)[2]), "+f"((c)[3]) \
        : "r"((a)[0]), "r"((a)[1]), "r"((a)[2]), "r"((a)[3]), "r"(b0), "r"(b1))

// ---------------- prep: dist_emb + h init (+ fp16 splits) + zero aggr ----------------
__global__ void prep_kernel(const int* __restrict__ dists,
                            const float* __restrict__ noise,
                            const float* __restrict__ dtab)
{
    int i = blockIdx.x * blockDim.x + threadIdx.x;
    if (i >= Bk*Nn*Dd/4) return;
    int node = i >> 5;
    int c = i & 31;
    int di = dists[node];
    di = di < 0 ? 0 : (di > 9 ? 9 : di);
    float4 dv = __ldg(((const float4*)(dtab + (size_t)di*Dd)) + c);
    float4 nz = ((const float4*)noise)[i];
    float4 h;
    h.x = dv.x + 0.1f*nz.x; h.y = dv.y + 0.1f*nz.y;
    h.z = dv.z + 0.1f*nz.z; h.w = dv.w + 0.1f*nz.w;
    ((float4*)g_de)[i] = dv;
    ((float4*)g_h)[i]  = h;
    ((float4*)g_aggr)[i] = make_float4(0.f, 0.f, 0.f, 0.f);

    __half2* p;
    __half a0, a1;
    a0 = __float2half_rn(h.x); a1 = __float2half_rn(h.y);
    p = (__half2*)g_hhi; p[2*i] = __halves2half2(a0, a1);
    p = (__half2*)g_hlo; p[2*i] = __halves2half2(__float2half_rn(h.x-__half2float(a0)), __float2half_rn(h.y-__half2float(a1)));
    a0 = __float2half_rn(h.z); a1 = __float2half_rn(h.w);
    p = (__half2*)g_hhi; p[2*i+1] = __halves2half2(a0, a1);
    p = (__half2*)g_hlo; p[2*i+1] = __halves2half2(__float2half_rn(h.z-__half2float(a0)), __float2half_rn(h.w-__half2float(a1)));
    a0 = __float2half_rn(dv.x); a1 = __float2half_rn(dv.y);
    p = (__half2*)g_dehi; p[2*i] = __halves2half2(a0, a1);
    p = (__half2*)g_delo; p[2*i] = __halves2half2(__float2half_rn(dv.x-__half2float(a0)), __float2half_rn(dv.y-__half2float(a1)));
    a0 = __float2half_rn(dv.z); a1 = __float2half_rn(dv.w);
    p = (__half2*)g_dehi; p[2*i+1] = __halves2half2(a0, a1);
    p = (__half2*)g_delo; p[2*i+1] = __halves2half2(__float2half_rn(dv.z-__half2float(a0)), __float2half_rn(dv.w-__half2float(a1)));
}

// ---------------- prep: conf + rel_table fp16 splits ----------------
__global__ void prep_aux(const float* __restrict__ conf, const float* __restrict__ rel_table)
{
    int i = blockIdx.x * blockDim.x + threadIdx.x;
    const int CT = Bk*Ee*Dd/4;
    float4 v; __half* hi; __half* lo; int base;
    if (i < CT) { v = ((const float4*)conf)[i]; hi = g_confhi; lo = g_conflo; base = i*4; }
    else {
        int j = i - CT;
        if (j >= Rr*Dd/4) return;
        v = ((const float4*)rel_table)[j]; hi = g_relhi; lo = g_rello; base = j*4;
    }
    __half a0 = __float2half_rn(v.x), a1 = __float2half_rn(v.y);
    __half a2 = __float2half_rn(v.z), a3 = __float2half_rn(v.w);
    *(__half2*)(hi + base)     = __halves2half2(a0, a1);
    *(__half2*)(hi + base + 2) = __halves2half2(a2, a3);
    *(__half2*)(lo + base)     = __halves2half2(__float2half_rn(v.x-__half2float(a0)), __float2half_rn(v.y-__half2float(a1)));
    *(__half2*)(lo + base + 2) = __halves2half2(__float2half_rn(v.z-__half2float(a2)), __float2half_rn(v.w-__half2float(a3)));
}

// ---------------- weight prep ----------------
__global__ void prep_weights(const float* __restrict__ msgW, const float* __restrict__ updW)
{
    int i = blockIdx.x * blockDim.x + threadIdx.x;
    const int MSGTOT = Ll*5*Dd*Dd;
    if (i < MSGTOT) {
        int l = i / (640*128);
        int k = (i / 128) % 640;
        int n = i & 127;
        int ch = k >> 5, kk = k & 31;
        float w = msgW[i];
        __half hi = __float2half_rn(w);
        __half lo = __float2half_rn(w - __half2float(hi));
        size_t o = (((size_t)(l*20 + ch))*128 + n)*32 + kk;
        g_msgWhi[o] = hi; g_msgWlo[o] = lo;
    } else {
        int j = i - MSGTOT;
        if (j < Ll*Dd*Dd) {
            int l = j / (128*128);
            int k = (j / 128) % 128;
            int n = j & 127;
            int ch = k >> 6, kk = k & 63;
            float w = updW[j];
            __half hi = __float2half_rn(w);
            __half lo = __float2half_rn(w - __half2float(hi));
            size_t o = (((size_t)(l*2 + ch))*128 + n)*64 + kk;
            g_updWhi[o] = hi; g_updWlo[o] = lo;
        }
    }
}

// ---------------- edge GEMM (R6 skeleton): 256 thr, 2-stage, B-frag double buffer ----------------
// CTA: 128 edges x 128 out, K=640 as 20 k32-chunks. 8 warps 4(M)x2(N), warp tile 32x64.
__global__ void __launch_bounds__(256, 2)
edge_hmma_kernel(int layer,
                 const int* __restrict__ edge_index,
                 const int* __restrict__ rels,
                 const int* __restrict__ edge_mask,
                 const float* __restrict__ rel_table,
                 const float* __restrict__ bias)
{
    extern __shared__ __half sm[];
    __shared__ int   s_src[128], s_tgt[128], s_rel[128];
    __shared__ float s_em[128], s_bias[128];

    int tid = threadIdx.x, wid = tid >> 5, lane = tid & 31;
    int b  = blockIdx.x >> 7;
    int e0 = (blockIdx.x & 127) << 7;

    if (tid < 128) {
        int e = e0 + tid;
        s_src[tid] = edge_index[(size_t)b*2*Ee + e];
        s_tgt[tid] = edge_index[(size_t)b*2*Ee + Ee + e];
        s_rel[tid] = rels[(size_t)b*Ee + e];
        s_em[tid]  = edge_mask[(size_t)b*Ee + e] ? 1.f : 0.f;
        s_bias[tid] = bias[tid];
    }
    __syncthreads();

    uint32_t smb = smem_u32(sm);
    size_t bN = (size_t)b * Nn;
    int wm = wid & 3, wn = wid >> 2;
    int g = lane >> 2, t4 = lane & 3;

    float acc[2][8][4];
    #pragma unroll
    for (int i = 0; i < 2; i++)
        #pragma unroll
        for (int j = 0; j < 8; j++)
            #pragma unroll
            for (int q = 0; q < 4; q++) acc[i][j][q] = 0.f;

    auto issue = [&](int c, int st){
        uint32_t sb = smb + (uint32_t)(st*STAGE_H)*2;
        int wc = (c < 16) ? c + 4 : c - 16;
        const __half* wh = g_msgWhi + ((size_t)(layer*20 + wc))*4096;
        const __half* wl = g_msgWlo + ((size_t)(layer*20 + wc))*4096;
        #pragma unroll
        for (int r = 0; r < 2; r++){
            int idx = tid + r*256;
            int n = idx >> 2, f = idx & 3;
            uint32_t d = sb + (uint32_t)(2*TILE_H + n*ESTR + f*8)*2;
            cpa16(d,              wh + n*32 + f*8);
            cpa16(d + TILE_H*2,   wl + n*32 + f*8);
        }
        if (c < 16){
            int sg = c >> 2;
            int koff = (c & 3)*CH;
            #pragma unroll
            for (int r = 0; r < 2; r++){
                int idx = tid + r*256;
                int e = idx >> 2, q = idx & 3;
                size_t rowoff;
                const __half *ph, *pl;
                if (sg == 0)      { rowoff = (bN + s_src[e])*Dd; ph = g_hhi;   pl = g_hlo; }
                else if (sg == 1) { rowoff = (bN + s_src[e])*Dd; ph = g_dehi;  pl = g_delo; }
                else if (sg == 2) { rowoff = (size_t)s_rel[e]*Dd; ph = g_relhi; pl = g_rello; }
                else              { rowoff = ((size_t)b*Ee + e0 + e)*Dd; ph = g_confhi; pl = g_conflo; }
                uint32_t d = sb + (uint32_t)(e*ESTR + q*8)*2;
                cpa16(d,            ph + rowoff + koff + q*8);
                cpa16(d + TILE_H*2, pl + rowoff + koff + q*8);
            }
        }
    };
    auto fill0 = [&](int c, int st){
        __half* base = sm + st*STAGE_H;
        int koff = (c - 16)*CH;
        #pragma unroll
        for (int r = 0; r < 2; r++){
            int idx = tid + r*256;
            int e = idx >> 2, q = idx & 3;
            const float* hp = g_h + (bN + s_src[e])*Dd + koff + q*8;
            const float* rp = rel_table + (size_t)s_rel[e]*Dd + koff + q*8;
            float4 h1 = *(const float4*)hp, h2 = *(const float4*)(hp + 4);
            float4 r1 = *(const float4*)rp, r2 = *(const float4*)(rp + 4);
            float pr[8] = {h1.x*r1.x, h1.y*r1.y, h1.z*r1.z, h1.w*r1.w,
                           h2.x*r2.x, h2.y*r2.y, h2.z*r2.z, h2.w*r2.w};
            __half hh[8], ll[8];
            #pragma unroll
            for (int u = 0; u < 8; u++){
                hh[u] = __float2half_rn(pr[u]);
                ll[u] = __float2half_rn(pr[u] - __half2float(hh[u]));
            }
            *(uint4*)(base + e*ESTR + q*8)          = *(uint4*)hh;
            *(uint4*)(base + TILE_H + e*ESTR + q*8) = *(uint4*)ll;
        }
    };

    issue(0, 0); CP_COMMIT();

    for (int c = 0; c < 20; c++){
        int st = c & 1, nst = st ^ 1;
        if (c + 1 < 20){
            issue(c + 1, nst);
            if (c + 1 >= 16) fill0(c + 1, nst);
            CP_COMMIT();
            asm volatile("cp.async.wait_group 1;" ::: "memory");
        } else {
            asm volatile("cp.async.wait_group 0;" ::: "memory");
        }
        __syncthreads();

        uint32_t sb = smb + (uint32_t)(st*STAGE_H)*2;
        #pragma unroll
        for (int k16 = 0; k16 < 2; k16++){
            int kb = k16*16;
            uint32_t ah[2][4], al[2][4];
            #pragma unroll
            for (int i = 0; i < 2; i++){
                uint32_t a = sb + (uint32_t)((wm*32 + i*16 + (lane & 15))*ESTR + kb + (lane >> 4)*8)*2;
                LDSM4(ah[i], a);
                LDSM4(al[i], a + TILE_H*2);
            }
            uint32_t bh[2][4], bl[2][4];
            {   // preload jp=0 B frags
                uint32_t bb = sb + (uint32_t)(2*TILE_H + (wn*64 + (lane & 15))*ESTR + kb + (lane >> 4)*8)*2;
                LDSM4(bh[0], bb);
                LDSM4(bl[0], bb + TILE_H*2);
            }
            #pragma unroll
            for (int jp = 0; jp < 4; jp++){
                int cur = jp & 1, nxt = cur ^ 1;
                if (jp < 3){    // prefetch next jp's B frags before MMAs
                    uint32_t bb = sb + (uint32_t)(2*TILE_H + (wn*64 + (jp+1)*16 + (lane & 15))*ESTR + kb + (lane >> 4)*8)*2;
                    LDSM4(bh[nxt], bb);
                    LDSM4(bl[nxt], bb + TILE_H*2);
                }
                // 12 MMAs, term-major: same-acc reuse distance 4
                MMA_F16(acc[0][jp*2+0], ah[0], bh[cur][0], bh[cur][2]);
                MMA_F16(acc[0][jp*2+1], ah[0], bh[cur][1], bh[cur][3]);
                MMA_F16(acc[1][jp*2+0], ah[1], bh[cur][0], bh[cur][2]);
                MMA_F16(acc[1][jp*2+1], ah[1], bh[cur][1], bh[cur][3]);
                MMA_F16(acc[0][jp*2+0], ah[0], bl[cur][0], bl[cur][2]);
                MMA_F16(acc[0][jp*2+1], ah[0], bl[cur][1], bl[cur][3]);
                MMA_F16(acc[1][jp*2+0], ah[1], bl[cur][0], bl[cur][2]);
                MMA_F16(acc[1][jp*2+1], ah[1], bl[cur][1], bl[cur][3]);
                MMA_F16(acc[0][jp*2+0], al[0], bh[cur][0], bh[cur][2]);
                MMA_F16(acc[0][jp*2+1], al[0], bh[cur][1], bh[cur][3]);
                MMA_F16(acc[1][jp*2+0], al[1], bh[cur][0], bh[cur][2]);
                MMA_F16(acc[1][jp*2+1], al[1], bh[cur][1], bh[cur][3]);
            }
        }
        __syncthreads();
    }

    // epilogue: relu + bias + mask, scatter-add (validated mapping)
    #pragma unroll
    for (int i = 0; i < 2; i++) {
        #pragma unroll
        for (int half = 0; half < 2; half++) {
            int row = wm*32 + i*16 + g + half*8;
            if (s_em[row] != 0.f) {
                float* dst = g_aggr + (bN + s_tgt[row])*Dd;
                #pragma unroll
                for (int j = 0; j < 8; j++) {
                    int col = wn*64 + j*8 + t4*2;
                    float v0 = acc[i][j][half*2+0] + s_bias[col];
                    float v1 = acc[i][j][half*2+1] + s_bias[col+1];
                    if (v0 > 0.f) atomicAdd(dst + col,     v0);
                    if (v1 > 0.f) atomicAdd(dst + col + 1, v1);
                }
            }
        }
    }
}

// ---------------- node update GEMM (validated) + fused h re-split + aggr re-zero ----------------
__global__ void __launch_bounds__(256, 2)
update_hmma_kernel(int layer, const float* __restrict__ bias)
{
    extern __shared__ __half sm[];
    __half* sAhi = sm;
    __half* sAlo = sAhi + 128*USTR;
    __half* sBhi = sAlo + 128*USTR;
    __half* sBlo = sBhi + 128*USTR;
    __shared__ float s_bias[128];

    int tid = threadIdx.x, wid = tid >> 5, lane = tid & 31;
    size_t r0 = (size_t)blockIdx.x * 128;
    if (tid < 128) s_bias[tid] = bias[tid];
    __syncthreads();

    int wm = wid & 3, wn = wid >> 2;
    int g = lane >> 2, t4 = lane & 3;

    float acc[2][8][4];
    #pragma unroll
    for (int i = 0; i < 2; i++)
        #pragma unroll
        for (int j = 0; j < 8; j++)
            #pragma unroll
            for (int q = 0; q < 4; q++) acc[i][j][q] = 0.f;

    for (int c = 0; c < 2; c++) {
        int koff = c*64;
        #pragma unroll
        for (int it = 0; it < 8; it++) {
            int idx = tid + it*256;
            int row = idx >> 4, q = idx & 15;
            float4* ap = (float4*)(g_aggr + (r0 + row)*Dd + koff + q*4);
            float4 v = *ap;
            *ap = make_float4(0.f, 0.f, 0.f, 0.f);   // re-zero for next layer (replaces memset)
            __half h0 = __float2half_rn(v.x), h1 = __float2half_rn(v.y);
            __half h2 = __float2half_rn(v.z), h3 = __float2half_rn(v.w);
            int ho = row*USTR + q*4;
            *(__half2*)(sAhi + ho)     = __halves2half2(h0, h1);
            *(__half2*)(sAhi + ho + 2) = __halves2half2(h2, h3);
            *(__half2*)(sAlo + ho)     = __halves2half2(__float2half_rn(v.x-__half2float(h0)), __float2half_rn(v.y-__half2float(h1)));
            *(__half2*)(sAlo + ho + 2) = __halves2half2(__float2half_rn(v.z-__half2float(h2)), __float2half_rn(v.w-__half2float(h3)));
        }
        {
            const uint4* wh = (const uint4*)(g_updWhi + ((size_t)(layer*2 + c))*8192);
            const uint4* wl = (const uint4*)(g_updWlo + ((size_t)(layer*2 + c))*8192);
            #pragma unroll
            for (int it = 0; it < 4; it++) {
                int idx = tid + it*256;
                int n = idx >> 3, q = idx & 7;
                *(uint4*)(sBhi + n*USTR + q*8) = __ldg(wh + idx);
                *(uint4*)(sBlo + n*USTR + q*8) = __ldg(wl + idx);
            }
        }
        __syncthreads();

        #pragma unroll
        for (int k16 = 0; k16 < 4; k16++) {
            int kb = k16*16;
            uint32_t ahi[2][4], alo[2][4];
            #pragma unroll
            for (int i = 0; i < 2; i++) {
                uint32_t a = smem_u32(sAhi + (wm*32 + i*16 + (lane & 15))*USTR + kb + (lane >> 4)*8);
                LDSM4(ahi[i], a);
                LDSM4(alo[i], a + 128*USTR*2);
            }
            #pragma unroll
            for (int jp = 0; jp < 4; jp++) {
                uint32_t bb = smem_u32(sBhi + (wn*64 + jp*16 + (lane & 15))*USTR + kb + (lane >> 4)*8);
                uint32_t bh[4], bl[4];
                LDSM4(bh, bb);
                LDSM4(bl, bb + 128*USTR*2);
                MMA_F16(acc[0][jp*2+0], ahi[0], bh[0], bh[2]);
                MMA_F16(acc[0][jp*2+1], ahi[0], bh[1], bh[3]);
                MMA_F16(acc[1][jp*2+0], ahi[1], bh[0], bh[2]);
                MMA_F16(acc[1][jp*2+1], ahi[1], bh[1], bh[3]);
                MMA_F16(acc[0][jp*2+0], ahi[0], bl[0], bl[2]);
                MMA_F16(acc[0][jp*2+1], ahi[0], bl[1], bl[3]);
                MMA_F16(acc[1][jp*2+0], ahi[1], bl[0], bl[2]);
                MMA_F16(acc[1][jp*2+1], ahi[1], bl[1], bl[3]);
                MMA_F16(acc[0][jp*2+0], alo[0], bh[0], bh[2]);
                MMA_F16(acc[0][jp*2+1], alo[0], bh[1], bh[3]);
                MMA_F16(acc[1][jp*2+0], alo[1], bh[0], bh[2]);
                MMA_F16(acc[1][jp*2+1], alo[1], bh[1], bh[3]);
            }
        }
        __syncthreads();
    }

    #pragma unroll
    for (int i = 0; i < 2; i++) {
        #pragma unroll
        for (int half = 0; half < 2; half++) {
            int row = wm*32 + i*16 + g + half*8;
            size_t gro = (r0 + row)*Dd;
            float* hp = g_h + gro;
            #pragma unroll
            for (int j = 0; j < 8; j++) {
                int col = wn*64 + j*8 + t4*2;
                float v0 = hp[col]     + acc[i][j][half*2+0] + s_bias[col];
                float v1 = hp[col + 1] + acc[i][j][half*2+1] + s_bias[col+1];
                hp[col] = v0; hp[col + 1] = v1;
                __half a0 = __float2half_rn(v0), a1 = __float2half_rn(v1);
                *(__half2*)(g_hhi + gro + col) = __halves2half2(a0, a1);
                *(__half2*)(g_hlo + gro + col) = __halves2half2(
                    __float2half_rn(v0 - __half2float(a0)),
                    __float2half_rn(v1 - __half2float(a1)));
            }
        }
    }
}

// ---------------- attention scores ----------------
__global__ void score_kernel(const float* __restrict__ attW, const float* __restrict__ attb,
                             const int* __restrict__ node_mask,
                             const float* __restrict__ rq)
{
    int gw = blockIdx.x*8 + (threadIdx.x >> 5);
    int lane = threadIdx.x & 31;
    int b = gw / Nn, n = gw % Nn;
    const float* hrow = g_h + (size_t)gw*Dd;
    float s = 0.f;
    #pragma unroll
    for (int i = 0; i < 4; i++) {
        int d = lane + i*32;
        s = fmaf(hrow[d], attW[d], s);
        s = fmaf(rq[b*Dd + d], attW[Dd + d], s);
    }
    #pragma unroll
    for (int o = 16; o; o >>= 1) s += __shfl_xor_sync(0xffffffffu, s, o);
    if (lane == 0) {
        s += attb[0];
        s = (s > 0.f) ? s : 0.01f * s;
        if (!node_mask[(size_t)b*Nn + n]) s = -1e9f;
        g_scores[gw] = s;
    }
}

// ---------------- softmax + top-20 + output (1 block / batch) ----------------
__global__ void __launch_bounds__(1024)
topk_kernel(const int* __restrict__ node_mask, float* __restrict__ out)
{
    __shared__ float ss[Nn];
    __shared__ float rv[1024];
    __shared__ int   ri[1024];
    __shared__ float s_max, s_sum;
    __shared__ int   top_i[Mm];
    __shared__ float top_v[Mm];

    int b = blockIdx.x;
    int t = threadIdx.x;

    for (int i = t; i < Nn; i += 1024) ss[i] = g_scores[(size_t)b*Nn + i];
    __syncthreads();

    float m = -INFINITY;
    for (int i = t; i < Nn; i += 1024) m = fmaxf(m, ss[i]);
    rv[t] = m; __syncthreads();
    for (int s = 512; s > 0; s >>= 1) { if (t < s) rv[t] = fmaxf(rv[t], rv[t+s]); __syncthreads(); }
    if (t == 0) s_max = rv[0];
    __syncthreads();
    float vmax = s_max;

    float sum = 0.f;
    for (int i = t; i < Nn; i += 1024) sum += expf(ss[i] - vmax);
    rv[t] = sum; __syncthreads();
    for (int s = 512; s > 0; s >>= 1) { if (t < s) rv[t] += rv[t+s]; __syncthreads(); }
    if (t == 0) s_sum = rv[0];
    __syncthreads();
    float inv = 1.f / s_sum;

    for (int sel = 0; sel < Mm; sel++) {
        float bv = -INFINITY; int bi = Nn;
        for (int i = t; i < Nn; i += 1024) {
            float v = ss[i];
            if (v > bv) { bv = v; bi = i; }
        }
        rv[t] = bv; ri[t] = bi; __syncthreads();
        for (int s = 512; s > 0; s >>= 1) {
            if (t < s) {
                if (rv[t+s] > rv[t] || (rv[t+s] == rv[t] && ri[t+s] < ri[t])) {
                    rv[t] = rv[t+s]; ri[t] = ri[t+s];
                }
            }
            __syncthreads();
        }
        if (t == 0) { top_i[sel] = ri[0]; top_v[sel] = rv[0]; ss[ri[0]] = -INFINITY; }
        __syncthreads();
    }

    for (int i = t; i < Mm*Dd; i += 1024) {
        int sel = i / Dd, d = i % Dd;
        int idx = top_i[sel];
        float alpha = expf(top_v[sel] - vmax) * inv;
        float mk = node_mask[(size_t)b*Nn + idx] ? 1.f : 0.f;
        float hv = g_h[((size_t)b*Nn + idx)*Dd + d] * mk;
        out[((size_t)b*Mm + sel)*Dd + d] = hv * alpha;
    }
    float m0 = node_mask[(size_t)b*Nn] ? 1.f : 0.f;
    for (int d = t; d < Dd; d += 1024)
        out[(size_t)Bk*Mm*Dd + (size_t)b*Dd + d] = g_h[((size_t)b*Nn)*Dd + d] * m0;
}

// ---------------- launch ----------------
extern "C" void kernel_launch(void* const* d_in, const int* in_sizes, int n_in,
                              void* d_out, int out_size)
{
    (void)in_sizes; (void)n_in; (void)out_size;
    const int*   dists      = (const int*)d_in[0];
    const int*   edge_index = (const int*)d_in[1];
    const int*   rels       = (const int*)d_in[2];
    const int*   node_mask  = (const int*)d_in[3];
    const int*   edge_mask  = (const int*)d_in[4];
    const float* rq         = (const float*)d_in[5];
    const float* conf       = (const float*)d_in[6];
    const float* noise      = (const float*)d_in[7];
    const float* dist_table = (const float*)d_in[8];
    const float* rel_table  = (const float*)d_in[9];
    const float* msg_W      = (const float*)d_in[10];
    const float* msg_b      = (const float*)d_in[11];
    const float* upd_W      = (const float*)d_in[12];
    const float* upd_b      = (const float*)d_in[13];
    const float* att_W      = (const float*)d_in[14];
    const float* att_b      = (const float*)d_in[15];
    float* out = (float*)d_out;

    cudaFuncSetAttribute(edge_hmma_kernel, cudaFuncAttributeMaxDynamicSharedMemorySize, ESMEM);
    cudaFuncSetAttribute(update_hmma_kernel, cudaFuncAttributeMaxDynamicSharedMemorySize, (int)USMEM);

    int total4 = Bk*Nn*Dd/4;
    prep_kernel<<<(total4 + 255)/256, 256>>>(dists, noise, dist_table);
    prep_aux<<<(Bk*Ee*Dd/4 + Rr*Dd/4 + 255)/256, 256>>>(conf, rel_table);
    prep_weights<<<(Ll*5*Dd*Dd + Ll*Dd*Dd + 255)/256, 256>>>(msg_W, upd_W);

    for (int l = 0; l < Ll; l++) {
        edge_hmma_kernel<<<Bk*(Ee/128), 256, ESMEM>>>(
            l, edge_index, rels, edge_mask, rel_table, msg_b + (size_t)l*Dd);
        update_hmma_kernel<<<Bk*Nn/128, 256, USMEM>>>(l, upd_b + (size_t)l*Dd);
    }

    score_kernel<<<Bk*Nn/8, 256>>>(att_W, att_b, node_mask, rq);
    topk_kernel<<<Bk, 1024>>>(node_mask, out);
}

// round 9
// speedup vs baseline: 1.4510x; 1.4287x over previous
#include <cuda_runtime.h>
#include <cuda_fp16.h>
#include <math.h>
#include <stdint.h>

#define Bk 8
#define Nn 8192
#define Ee 16384
#define Dd 128
#define Mm 20
#define Ll 3
#define Rr 200

// ---- edge kernel geometry ----
#define CH 32
#define ESTR 40
#define TILE_H (128*ESTR)
#define STAGE_H (4*TILE_H)
#define ESMEM (2*STAGE_H*2)      // 81920 bytes, 2 stages
#define NCH 12                   // K=384: 4 h + 4 conf + 4 comp

// ---- update kernel geometry (validated) ----
#define USTR 72
#define USMEM ((size_t)(4*128*USTR)*2)

// -------- device scratch --------
__device__ float g_h[(size_t)Bk*Nn*Dd];
__device__ float g_de[(size_t)Bk*Nn*Dd];
__device__ float g_aggr[(size_t)Bk*Nn*Dd];
__device__ float g_scores[Bk*Nn];
__device__ float g_tblD[Ll*10*Dd];         // dist_table @ W3
__device__ float g_tblR[Ll*Rr*Dd];         // rel_table  @ W4
__device__ __half g_hhi[(size_t)Bk*Nn*Dd],  g_hlo[(size_t)Bk*Nn*Dd];
__device__ __half g_confhi[(size_t)Bk*Ee*Dd], g_conflo[(size_t)Bk*Ee*Dd];
__device__ __half g_msgWhi[(size_t)Ll*20*128*32], g_msgWlo[(size_t)Ll*20*128*32];
__device__ __half g_updWhi[(size_t)Ll*2*128*64],  g_updWlo[(size_t)Ll*2*128*64];

__device__ __forceinline__ uint32_t smem_u32(const void* p){
    uint32_t a;
    asm("{ .reg .u64 t; cvta.to.shared.u64 t, %1; cvt.u32.u64 %0, t; }" : "=r"(a) : "l"(p));
    return a;
}
__device__ __forceinline__ void cpa16(uint32_t dst, const void* src){
    asm volatile("cp.async.cg.shared.global [%0], [%1], 16;" :: "r"(dst), "l"(src));
}
#define CP_COMMIT() asm volatile("cp.async.commit_group;" ::: "memory")

#define LDSM4(r, addr) \
    asm volatile("ldmatrix.sync.aligned.m8n8.x4.shared.b16 {%0,%1,%2,%3}, [%4];" \
        : "=r"((r)[0]), "=r"((r)[1]), "=r"((r)[2]), "=r"((r)[3]) : "r"(addr))

#define MMA_F16(c, a, b0, b1) \
    asm volatile("mma.sync.aligned.m16n8k16.row.col.f32.f16.f16.f32 " \
        "{%0,%1,%2,%3}, {%4,%5,%6,%7}, {%8,%9}, {%0,%1,%2,%3};" \
        : "+f"((c)[0]), "+f"((c)[1]), "+f"((c)[2]), "+f"((c)[3]) \
        : "r"((a)[0]), "r"((a)[1]), "r"((a)[2]), "r"((a)[3]), "r"(b0), "r"(b1))

// ---------------- prep: dist_emb + h init (+ fp16 splits) ----------------
__global__ void prep_kernel(const int* __restrict__ dists,
                            const float* __restrict__ noise,
                            const float* __restrict__ dtab)
{
    int i = blockIdx.x * blockDim.x + threadIdx.x;
    if (i >= Bk*Nn*Dd/4) return;
    int node = i >> 5;
    int c = i & 31;
    int di = dists[node];
    di = di < 0 ? 0 : (di > 9 ? 9 : di);
    float4 dv = __ldg(((const float4*)(dtab + (size_t)di*Dd)) + c);
    float4 nz = ((const float4*)noise)[i];
    float4 h;
    h.x = dv.x + 0.1f*nz.x; h.y = dv.y + 0.1f*nz.y;
    h.z = dv.z + 0.1f*nz.z; h.w = dv.w + 0.1f*nz.w;
    ((float4*)g_de)[i] = dv;
    ((float4*)g_h)[i]  = h;

    __half2* p;
    __half a0, a1;
    a0 = __float2half_rn(h.x); a1 = __float2half_rn(h.y);
    p = (__half2*)g_hhi; p[2*i] = __halves2half2(a0, a1);
    p = (__half2*)g_hlo; p[2*i] = __halves2half2(__float2half_rn(h.x-__half2float(a0)), __float2half_rn(h.y-__half2float(a1)));
    a0 = __float2half_rn(h.z); a1 = __float2half_rn(h.w);
    p = (__half2*)g_hhi; p[2*i+1] = __halves2half2(a0, a1);
    p = (__half2*)g_hlo; p[2*i+1] = __halves2half2(__float2half_rn(h.z-__half2float(a0)), __float2half_rn(h.w-__half2float(a1)));
}

// ---------------- prep: conf fp16 split ----------------
__global__ void prep_aux(const float* __restrict__ conf)
{
    int i = blockIdx.x * blockDim.x + threadIdx.x;
    if (i >= Bk*Ee*Dd/4) return;
    float4 v = ((const float4*)conf)[i];
    int base = i*4;
    __half a0 = __float2half_rn(v.x), a1 = __float2half_rn(v.y);
    __half a2 = __float2half_rn(v.z), a3 = __float2half_rn(v.w);
    *(__half2*)(g_confhi + base)     = __halves2half2(a0, a1);
    *(__half2*)(g_confhi + base + 2) = __halves2half2(a2, a3);
    *(__half2*)(g_conflo + base)     = __halves2half2(__float2half_rn(v.x-__half2float(a0)), __float2half_rn(v.y-__half2float(a1)));
    *(__half2*)(g_conflo + base + 2) = __halves2half2(__float2half_rn(v.z-__half2float(a2)), __float2half_rn(v.w-__half2float(a3)));
}

// ---------------- weight prep ----------------
__global__ void prep_weights(const float* __restrict__ msgW, const float* __restrict__ updW)
{
    int i = blockIdx.x * blockDim.x + threadIdx.x;
    const int MSGTOT = Ll*5*Dd*Dd;
    if (i < MSGTOT) {
        int l = i / (640*128);
        int k = (i / 128) % 640;
        int n = i & 127;
        int ch = k >> 5, kk = k & 31;
        float w = msgW[i];
        __half hi = __float2half_rn(w);
        __half lo = __float2half_rn(w - __half2float(hi));
        size_t o = (((size_t)(l*20 + ch))*128 + n)*32 + kk;
        g_msgWhi[o] = hi; g_msgWlo[o] = lo;
    } else {
        int j = i - MSGTOT;
        if (j < Ll*Dd*Dd) {
            int l = j / (128*128);
            int k = (j / 128) % 128;
            int n = j & 127;
            int ch = k >> 6, kk = k & 63;
            float w = updW[j];
            __half hi = __float2half_rn(w);
            __half lo = __float2half_rn(w - __half2float(hi));
            size_t o = (((size_t)(l*2 + ch))*128 + n)*64 + kk;
            g_updWhi[o] = hi; g_updWlo[o] = lo;
        }
    }
}

// ---------------- table prep: tblD = dist_table@W3, tblR = rel_table@W4 (fp32 exact) ----------------
__global__ void prep_tbl(const float* __restrict__ dtab,
                         const float* __restrict__ rel_table,
                         const float* __restrict__ msgW)
{
    int i = blockIdx.x * blockDim.x + threadIdx.x;
    if (i >= Ll*(10+Rr)*Dd) return;
    int n = i & 127;
    int row = (i >> 7) % (10+Rr);
    int l = i / ((10+Rr)*Dd);
    const float* Wl = msgW + (size_t)l*640*128;
    float s = 0.f;
    if (row < 10) {
        const float* dr = dtab + row*Dd;
        const float* w = Wl + (size_t)2*128*128;      // seg 2 (dist_src)
        #pragma unroll 4
        for (int k = 0; k < 128; k++) s = fmaf(dr[k], w[(size_t)k*128 + n], s);
        g_tblD[(l*10 + row)*Dd + n] = s;
    } else {
        int r = row - 10;
        const float* rr = rel_table + (size_t)r*Dd;
        const float* w = Wl + (size_t)3*128*128;      // seg 3 (h_r)
        #pragma unroll 4
        for (int k = 0; k < 128; k++) s = fmaf(rr[k], w[(size_t)k*128 + n], s);
        g_tblR[((size_t)l*Rr + r)*Dd + n] = s;
    }
}

// ---------------- edge GEMM: K=384 (comp, h_src, conf), table epilogue ----------------
// CTA: 128 edges x 128 out, 12 k32-chunks. 8 warps 4(M)x2(N), warp tile 32x64.
// chunks 0-3: h_src (copy), 4-7: conf (copy), 8-11: comp (computed fill)
__global__ void __launch_bounds__(256, 2)
edge_hmma_kernel(int layer,
                 const int* __restrict__ edge_index,
                 const int* __restrict__ rels,
                 const int* __restrict__ edge_mask,
                 const int* __restrict__ dists,
                 const float* __restrict__ rel_table,
                 const float* __restrict__ bias)
{
    extern __shared__ __half sm[];
    __shared__ int   s_src[128], s_tgt[128], s_rel[128], s_di[128];
    __shared__ float s_em[128], s_bias[128];

    int tid = threadIdx.x, wid = tid >> 5, lane = tid & 31;
    int b  = blockIdx.x >> 7;
    int e0 = (blockIdx.x & 127) << 7;
    size_t bN = (size_t)b * Nn;

    if (tid < 128) {
        int e = e0 + tid;
        int src = edge_index[(size_t)b*2*Ee + e];
        s_src[tid] = src;
        s_tgt[tid] = edge_index[(size_t)b*2*Ee + Ee + e];
        s_rel[tid] = rels[(size_t)b*Ee + e];
        s_em[tid]  = edge_mask[(size_t)b*Ee + e] ? 1.f : 0.f;
        s_bias[tid] = bias[tid];
        int di = dists[bN + src];
        s_di[tid] = di < 0 ? 0 : (di > 9 ? 9 : di);
    }
    __syncthreads();

    uint32_t smb = smem_u32(sm);
    int wm = wid & 3, wn = wid >> 2;
    int g = lane >> 2, t4 = lane & 3;

    float acc[2][8][4];
    #pragma unroll
    for (int i = 0; i < 2; i++)
        #pragma unroll
        for (int j = 0; j < 8; j++)
            #pragma unroll
            for (int q = 0; q < 4; q++) acc[i][j][q] = 0.f;

    auto issue = [&](int c, int st){
        uint32_t sb = smb + (uint32_t)(st*STAGE_H)*2;
        // weight chunk remap: c<4 -> seg1 (4+c); c<8 -> seg4 (16+c-4); else seg0 (c-8)
        int wc = (c < 4) ? (4 + c) : ((c < 8) ? (12 + c) : (c - 8));
        const __half* wh = g_msgWhi + ((size_t)(layer*20 + wc))*4096;
        const __half* wl = g_msgWlo + ((size_t)(layer*20 + wc))*4096;
        #pragma unroll
        for (int r = 0; r < 2; r++){
            int idx = tid + r*256;
            int n = idx >> 2, f = idx & 3;
            uint32_t d = sb + (uint32_t)(2*TILE_H + n*ESTR + f*8)*2;
            cpa16(d,              wh + n*32 + f*8);
            cpa16(d + TILE_H*2,   wl + n*32 + f*8);
        }
        if (c < 8){
            int koff = (c & 3)*CH;
            #pragma unroll
            for (int r = 0; r < 2; r++){
                int idx = tid + r*256;
                int e = idx >> 2, q = idx & 3;
                size_t rowoff;
                const __half *ph, *pl;
                if (c < 4) { rowoff = (bN + s_src[e])*Dd; ph = g_hhi; pl = g_hlo; }
                else       { rowoff = ((size_t)b*Ee + e0 + e)*Dd; ph = g_confhi; pl = g_conflo; }
                uint32_t d = sb + (uint32_t)(e*ESTR + q*8)*2;
                cpa16(d,            ph + rowoff + koff + q*8);
                cpa16(d + TILE_H*2, pl + rowoff + koff + q*8);
            }
        }
    };
    auto fill0 = [&](int c, int st){
        __half* base = sm + st*STAGE_H;
        int koff = (c - 8)*CH;
        #pragma unroll
        for (int r = 0; r < 2; r++){
            int idx = tid + r*256;
            int e = idx >> 2, q = idx & 3;
            const float* hp = g_h + (bN + s_src[e])*Dd + koff + q*8;
            const float* rp = rel_table + (size_t)s_rel[e]*Dd + koff + q*8;
            float4 h1 = *(const float4*)hp, h2 = *(const float4*)(hp + 4);
            float4 r1 = *(const float4*)rp, r2 = *(const float4*)(rp + 4);
            float pr[8] = {h1.x*r1.x, h1.y*r1.y, h1.z*r1.z, h1.w*r1.w,
                           h2.x*r2.x, h2.y*r2.y, h2.z*r2.z, h2.w*r2.w};
            __half hh[8], ll[8];
            #pragma unroll
            for (int u = 0; u < 8; u++){
                hh[u] = __float2half_rn(pr[u]);
                ll[u] = __float2half_rn(pr[u] - __half2float(hh[u]));
            }
            *(uint4*)(base + e*ESTR + q*8)          = *(uint4*)hh;
            *(uint4*)(base + TILE_H + e*ESTR + q*8) = *(uint4*)ll;
        }
    };

    issue(0, 0); CP_COMMIT();

    for (int c = 0; c < NCH; c++){
        int st = c & 1, nst = st ^ 1;
        if (c + 1 < NCH){
            issue(c + 1, nst);
            if (c + 1 >= 8) fill0(c + 1, nst);
            CP_COMMIT();
            asm volatile("cp.async.wait_group 1;" ::: "memory");
        } else {
            asm volatile("cp.async.wait_group 0;" ::: "memory");
        }
        __syncthreads();

        uint32_t sb = smb + (uint32_t)(st*STAGE_H)*2;
        #pragma unroll
        for (int k16 = 0; k16 < 2; k16++){
            int kb = k16*16;
            uint32_t ah[2][4], al[2][4];
            #pragma unroll
            for (int i = 0; i < 2; i++){
                uint32_t a = sb + (uint32_t)((wm*32 + i*16 + (lane & 15))*ESTR + kb + (lane >> 4)*8)*2;
                LDSM4(ah[i], a);
                LDSM4(al[i], a + TILE_H*2);
            }
            uint32_t bh[2][4], bl[2][4];
            {
                uint32_t bb = sb + (uint32_t)(2*TILE_H + (wn*64 + (lane & 15))*ESTR + kb + (lane >> 4)*8)*2;
                LDSM4(bh[0], bb);
                LDSM4(bl[0], bb + TILE_H*2);
            }
            #pragma unroll
            for (int jp = 0; jp < 4; jp++){
                int cur = jp & 1, nxt = cur ^ 1;
                if (jp < 3){
                    uint32_t bb = sb + (uint32_t)(2*TILE_H + (wn*64 + (jp+1)*16 + (lane & 15))*ESTR + kb + (lane >> 4)*8)*2;
                    LDSM4(bh[nxt], bb);
                    LDSM4(bl[nxt], bb + TILE_H*2);
                }
                MMA_F16(acc[0][jp*2+0], ah[0], bh[cur][0], bh[cur][2]);
                MMA_F16(acc[0][jp*2+1], ah[0], bh[cur][1], bh[cur][3]);
                MMA_F16(acc[1][jp*2+0], ah[1], bh[cur][0], bh[cur][2]);
                MMA_F16(acc[1][jp*2+1], ah[1], bh[cur][1], bh[cur][3]);
                MMA_F16(acc[0][jp*2+0], ah[0], bl[cur][0], bl[cur][2]);
                MMA_F16(acc[0][jp*2+1], ah[0], bl[cur][1], bl[cur][3]);
                MMA_F16(acc[1][jp*2+0], ah[1], bl[cur][0], bl[cur][2]);
                MMA_F16(acc[1][jp*2+1], ah[1], bl[cur][1], bl[cur][3]);
                MMA_F16(acc[0][jp*2+0], al[0], bh[cur][0], bh[cur][2]);
                MMA_F16(acc[0][jp*2+1], al[0], bh[cur][1], bh[cur][3]);
                MMA_F16(acc[1][jp*2+0], al[1], bh[cur][0], bh[cur][2]);
                MMA_F16(acc[1][jp*2+1], al[1], bh[cur][1], bh[cur][3]);
            }
        }
        __syncthreads();
    }

    // epilogue: acc + bias + tblD[dist_src] + tblR[rel] -> relu -> masked scatter-add
    #pragma unroll
    for (int i = 0; i < 2; i++) {
        #pragma unroll
        for (int half = 0; half < 2; half++) {
            int row = wm*32 + i*16 + g + half*8;
            if (s_em[row] != 0.f) {
                const float* tD = g_tblD + (layer*10 + s_di[row])*Dd;
                const float* tR = g_tblR + ((size_t)layer*Rr + s_rel[row])*Dd;
                float* dst = g_aggr + (bN + s_tgt[row])*Dd;
                #pragma unroll
                for (int j = 0; j < 8; j++) {
                    int col = wn*64 + j*8 + t4*2;
                    float add0 = s_bias[col]   + __ldg(tD + col)     + __ldg(tR + col);
                    float add1 = s_bias[col+1] + __ldg(tD + col + 1) + __ldg(tR + col + 1);
                    float v0 = acc[i][j][half*2+0] + add0;
                    float v1 = acc[i][j][half*2+1] + add1;
                    if (v0 > 0.f) atomicAdd(dst + col,     v0);
                    if (v1 > 0.f) atomicAdd(dst + col + 1, v1);
                }
            }
        }
    }
}

// ---------------- node update GEMM (validated R6) + fused h re-split ----------------
__global__ void __launch_bounds__(256, 2)
update_hmma_kernel(int layer, const float* __restrict__ bias)
{
    extern __shared__ __half sm[];
    __half* sAhi = sm;
    __half* sAlo = sAhi + 128*USTR;
    __half* sBhi = sAlo + 128*USTR;
    __half* sBlo = sBhi + 128*USTR;
    __shared__ float s_bias[128];

    int tid = threadIdx.x, wid = tid >> 5, lane = tid & 31;
    size_t r0 = (size_t)blockIdx.x * 128;
    if (tid < 128) s_bias[tid] = bias[tid];
    __syncthreads();

    int wm = wid & 3, wn = wid >> 2;
    int g = lane >> 2, t4 = lane & 3;

    float acc[2][8][4];
    #pragma unroll
    for (int i = 0; i < 2; i++)
        #pragma unroll
        for (int j = 0; j < 8; j++)
            #pragma unroll
            for (int q = 0; q < 4; q++) acc[i][j][q] = 0.f;

    for (int c = 0; c < 2; c++) {
        int koff = c*64;
        #pragma unroll
        for (int it = 0; it < 8; it++) {
            int idx = tid + it*256;
            int row = idx >> 4, q = idx & 15;
            float4 v = *(const float4*)(g_aggr + (r0 + row)*Dd + koff + q*4);
            __half h0 = __float2half_rn(v.x), h1 = __float2half_rn(v.y);
            __half h2 = __float2half_rn(v.z), h3 = __float2half_rn(v.w);
            int ho = row*USTR + q*4;
            *(__half2*)(sAhi + ho)     = __halves2half2(h0, h1);
            *(__half2*)(sAhi + ho + 2) = __halves2half2(h2, h3);
            *(__half2*)(sAlo + ho)     = __halves2half2(__float2half_rn(v.x-__half2float(h0)), __float2half_rn(v.y-__half2float(h1)));
            *(__half2*)(sAlo + ho + 2) = __halves2half2(__float2half_rn(v.z-__half2float(h2)), __float2half_rn(v.w-__half2float(h3)));
        }
        {
            const uint4* wh = (const uint4*)(g_updWhi + ((size_t)(layer*2 + c))*8192);
            const uint4* wl = (const uint4*)(g_updWlo + ((size_t)(layer*2 + c))*8192);
            #pragma unroll
            for (int it = 0; it < 4; it++) {
                int idx = tid + it*256;
                int n = idx >> 3, q = idx & 7;
                *(uint4*)(sBhi + n*USTR + q*8) = __ldg(wh + idx);
                *(uint4*)(sBlo + n*USTR + q*8) = __ldg(wl + idx);
            }
        }
        __syncthreads();

        #pragma unroll
        for (int k16 = 0; k16 < 4; k16++) {
            int kb = k16*16;
            uint32_t ahi[2][4], alo[2][4];
            #pragma unroll
            for (int i = 0; i < 2; i++) {
                uint32_t a = smem_u32(sAhi + (wm*32 + i*16 + (lane & 15))*USTR + kb + (lane >> 4)*8);
                LDSM4(ahi[i], a);
                LDSM4(alo[i], a + 128*USTR*2);
            }
            #pragma unroll
            for (int jp = 0; jp < 4; jp++) {
                uint32_t bb = smem_u32(sBhi + (wn*64 + jp*16 + (lane & 15))*USTR + kb + (lane >> 4)*8);
                uint32_t bh[4], bl[4];
                LDSM4(bh, bb);
                LDSM4(bl, bb + 128*USTR*2);
                MMA_F16(acc[0][jp*2+0], ahi[0], bh[0], bh[2]);
                MMA_F16(acc[0][jp*2+1], ahi[0], bh[1], bh[3]);
                MMA_F16(acc[1][jp*2+0], ahi[1], bh[0], bh[2]);
                MMA_F16(acc[1][jp*2+1], ahi[1], bh[1], bh[3]);
                MMA_F16(acc[0][jp*2+0], ahi[0], bl[0], bl[2]);
                MMA_F16(acc[0][jp*2+1], ahi[0], bl[1], bl[3]);
                MMA_F16(acc[1][jp*2+0], ahi[1], bl[0], bl[2]);
                MMA_F16(acc[1][jp*2+1], ahi[1], bl[1], bl[3]);
                MMA_F16(acc[0][jp*2+0], alo[0], bh[0], bh[2]);
                MMA_F16(acc[0][jp*2+1], alo[0], bh[1], bh[3]);
                MMA_F16(acc[1][jp*2+0], alo[1], bh[0], bh[2]);
                MMA_F16(acc[1][jp*2+1], alo[1], bh[1], bh[3]);
            }
        }
        __syncthreads();
    }

    #pragma unroll
    for (int i = 0; i < 2; i++) {
        #pragma unroll
        for (int half = 0; half < 2; half++) {
            int row = wm*32 + i*16 + g + half*8;
            size_t gro = (r0 + row)*Dd;
            float* hp = g_h + gro;
            #pragma unroll
            for (int j = 0; j < 8; j++) {
                int col = wn*64 + j*8 + t4*2;
                float v0 = hp[col]     + acc[i][j][half*2+0] + s_bias[col];
                float v1 = hp[col + 1] + acc[i][j][half*2+1] + s_bias[col+1];
                hp[col] = v0; hp[col + 1] = v1;
                __half a0 = __float2half_rn(v0), a1 = __float2half_rn(v1);
                *(__half2*)(g_hhi + gro + col) = __halves2half2(a0, a1);
                *(__half2*)(g_hlo + gro + col) = __halves2half2(
                    __float2half_rn(v0 - __half2float(a0)),
                    __float2half_rn(v1 - __half2float(a1)));
            }
        }
    }
}

// ---------------- attention scores ----------------
__global__ void score_kernel(const float* __restrict__ attW, const float* __restrict__ attb,
                             const int* __restrict__ node_mask,
                             const float* __restrict__ rq)
{
    int gw = blockIdx.x*8 + (threadIdx.x >> 5);
    int lane = threadIdx.x & 31;
    int b = gw / Nn, n = gw % Nn;
    const float* hrow = g_h + (size_t)gw*Dd;
    float s = 0.f;
    #pragma unroll
    for (int i = 0; i < 4; i++) {
        int d = lane + i*32;
        s = fmaf(hrow[d], attW[d], s);
        s = fmaf(rq[b*Dd + d], attW[Dd + d], s);
    }
    #pragma unroll
    for (int o = 16; o; o >>= 1) s += __shfl_xor_sync(0xffffffffu, s, o);
    if (lane == 0) {
        s += attb[0];
        s = (s > 0.f) ? s : 0.01f * s;
        if (!node_mask[(size_t)b*Nn + n]) s = -1e9f;
        g_scores[gw] = s;
    }
}

// ---------------- softmax + top-20 + output (1 block / batch) ----------------
__global__ void __launch_bounds__(1024)
topk_kernel(const int* __restrict__ node_mask, float* __restrict__ out)
{
    __shared__ float ss[Nn];
    __shared__ float rv[1024];
    __shared__ int   ri[1024];
    __shared__ float s_max, s_sum;
    __shared__ int   top_i[Mm];
    __shared__ float top_v[Mm];

    int b = blockIdx.x;
    int t = threadIdx.x;

    for (int i = t; i < Nn; i += 1024) ss[i] = g_scores[(size_t)b*Nn + i];
    __syncthreads();

    float m = -INFINITY;
    for (int i = t; i < Nn; i += 1024) m = fmaxf(m, ss[i]);
    rv[t] = m; __syncthreads();
    for (int s = 512; s > 0; s >>= 1) { if (t < s) rv[t] = fmaxf(rv[t], rv[t+s]); __syncthreads(); }
    if (t == 0) s_max = rv[0];
    __syncthreads();
    float vmax = s_max;

    float sum = 0.f;
    for (int i = t; i < Nn; i += 1024) sum += expf(ss[i] - vmax);
    rv[t] = sum; __syncthreads();
    for (int s = 512; s > 0; s >>= 1) { if (t < s) rv[t] += rv[t+s]; __syncthreads(); }
    if (t == 0) s_sum = rv[0];
    __syncthreads();
    float inv = 1.f / s_sum;

    for (int sel = 0; sel < Mm; sel++) {
        float bv = -INFINITY; int bi = Nn;
        for (int i = t; i < Nn; i += 1024) {
            float v = ss[i];
            if (v > bv) { bv = v; bi = i; }
        }
        rv[t] = bv; ri[t] = bi; __syncthreads();
        for (int s = 512; s > 0; s >>= 1) {
            if (t < s) {
                if (rv[t+s] > rv[t] || (rv[t+s] == rv[t] && ri[t+s] < ri[t])) {
                    rv[t] = rv[t+s]; ri[t] = ri[t+s];
                }
            }
            __syncthreads();
        }
        if (t == 0) { top_i[sel] = ri[0]; top_v[sel] = rv[0]; ss[ri[0]] = -INFINITY; }
        __syncthreads();
    }

    for (int i = t; i < Mm*Dd; i += 1024) {
        int sel = i / Dd, d = i % Dd;
        int idx = top_i[sel];
        float alpha = expf(top_v[sel] - vmax) * inv;
        float mk = node_mask[(size_t)b*Nn + idx] ? 1.f : 0.f;
        float hv = g_h[((size_t)b*Nn + idx)*Dd + d] * mk;
        out[((size_t)b*Mm + sel)*Dd + d] = hv * alpha;
    }
    float m0 = node_mask[(size_t)b*Nn] ? 1.f : 0.f;
    for (int d = t; d < Dd; d += 1024)
        out[(size_t)Bk*Mm*Dd + (size_t)b*Dd + d] = g_h[((size_t)b*Nn)*Dd + d] * m0;
}

// ---------------- launch ----------------
extern "C" void kernel_launch(void* const* d_in, const int* in_sizes, int n_in,
                              void* d_out, int out_size)
{
    (void)in_sizes; (void)n_in; (void)out_size;
    const int*   dists      = (const int*)d_in[0];
    const int*   edge_index = (const int*)d_in[1];
    const int*   rels       = (const int*)d_in[2];
    const int*   node_mask  = (const int*)d_in[3];
    const int*   edge_mask  = (const int*)d_in[4];
    const float* rq         = (const float*)d_in[5];
    const float* conf       = (const float*)d_in[6];
    const float* noise      = (const float*)d_in[7];
    const float* dist_table = (const float*)d_in[8];
    const float* rel_table  = (const float*)d_in[9];
    const float* msg_W      = (const float*)d_in[10];
    const float* msg_b      = (const float*)d_in[11];
    const float* upd_W      = (const float*)d_in[12];
    const float* upd_b      = (const float*)d_in[13];
    const float* att_W      = (const float*)d_in[14];
    const float* att_b      = (const float*)d_in[15];
    float* out = (float*)d_out;

    cudaFuncSetAttribute(edge_hmma_kernel, cudaFuncAttributeMaxDynamicSharedMemorySize, ESMEM);
    cudaFuncSetAttribute(update_hmma_kernel, cudaFuncAttributeMaxDynamicSharedMemorySize, (int)USMEM);
    void* aggr_ptr = nullptr;
    cudaGetSymbolAddress(&aggr_ptr, g_aggr);

    int total4 = Bk*Nn*Dd/4;
    prep_kernel<<<(total4 + 255)/256, 256>>>(dists, noise, dist_table);
    prep_aux<<<(Bk*Ee*Dd/4 + 255)/256, 256>>>(conf);
    prep_weights<<<(Ll*5*Dd*Dd + Ll*Dd*Dd + 255)/256, 256>>>(msg_W, upd_W);
    prep_tbl<<<(Ll*(10+Rr)*Dd + 255)/256, 256>>>(dist_table, rel_table, msg_W);

    for (int l = 0; l < Ll; l++) {
        cudaMemsetAsync(aggr_ptr, 0, sizeof(float)*(size_t)Bk*Nn*Dd);
        edge_hmma_kernel<<<Bk*(Ee/128), 256, ESMEM>>>(
            l, edge_index, rels, edge_mask, dists, rel_table, msg_b + (size_t)l*Dd);
        update_hmma_kernel<<<Bk*Nn/128, 256, USMEM>>>(l, upd_b + (size_t)l*Dd);
    }

    score_kernel<<<Bk*Nn/8, 256>>>(att_W, att_b, node_mask, rq);
    topk_kernel<<<Bk, 1024>>>(node_mask, out);
}

// round 10
// speedup vs baseline: 1.5246x; 1.0507x over previous
#include <cuda_runtime.h>
#include <cuda_fp16.h>
#include <math.h>
#include <stdint.h>

#define Bk 8
#define Nn 8192
#define Ee 16384
#define Dd 128
#define Mm 20
#define Ll 3
#define Rr 200

// ---- edge kernel geometry ----
#define CH 32
#define ESTR 40
#define TILE_H (128*ESTR)
#define STAGE_H (4*TILE_H)
#define ESMEM (2*STAGE_H*2)      // 81920 bytes, 2 stages
#define NCH 12                   // K=384: 4 h + 4 conf + 4 comp

// ---- update kernel geometry (validated) ----
#define USTR 72
#define USMEM ((size_t)(4*128*USTR)*2)

// -------- device scratch --------
__device__ float g_h[(size_t)Bk*Nn*Dd];
__device__ float g_aggr[Ll][(size_t)Bk*Nn*Dd];   // one per layer; zeroed in prep
__device__ float g_scores[Bk*Nn];
__device__ float g_tblD[Ll*10*Dd];
__device__ float g_tblR[Ll*Rr*Dd];
__device__ __half g_hhi[(size_t)Bk*Nn*Dd],  g_hlo[(size_t)Bk*Nn*Dd];
__device__ __half g_confhi[(size_t)Bk*Ee*Dd], g_conflo[(size_t)Bk*Ee*Dd];
__device__ __half g_msgWhi[(size_t)Ll*20*128*32], g_msgWlo[(size_t)Ll*20*128*32];
__device__ __half g_updWhi[(size_t)Ll*2*128*64],  g_updWlo[(size_t)Ll*2*128*64];

__device__ __forceinline__ uint32_t smem_u32(const void* p){
    uint32_t a;
    asm("{ .reg .u64 t; cvta.to.shared.u64 t, %1; cvt.u32.u64 %0, t; }" : "=r"(a) : "l"(p));
    return a;
}
__device__ __forceinline__ void cpa16(uint32_t dst, const void* src){
    asm volatile("cp.async.cg.shared.global [%0], [%1], 16;" :: "r"(dst), "l"(src));
}
#define CP_COMMIT() asm volatile("cp.async.commit_group;" ::: "memory")

#define LDSM4(r, addr) \
    asm volatile("ldmatrix.sync.aligned.m8n8.x4.shared.b16 {%0,%1,%2,%3}, [%4];" \
        : "=r"((r)[0]), "=r"((r)[1]), "=r"((r)[2]), "=r"((r)[3]) : "r"(addr))

#define MMA_F16(c, a, b0, b1) \
    asm volatile("mma.sync.aligned.m16n8k16.row.col.f32.f16.f16.f32 " \
        "{%0,%1,%2,%3}, {%4,%5,%6,%7}, {%8,%9}, {%0,%1,%2,%3};" \
        : "+f"((c)[0]), "+f"((c)[1]), "+f"((c)[2]), "+f"((c)[3]) \
        : "r"((a)[0]), "r"((a)[1]), "r"((a)[2]), "r"((a)[3]), "r"(b0), "r"(b1))

// ---------------- prep: h init + fp16 splits + zero all aggr buffers ----------------
__global__ void prep_kernel(const int* __restrict__ dists,
                            const float* __restrict__ noise,
                            const float* __restrict__ dtab)
{
    int i = blockIdx.x * blockDim.x + threadIdx.x;
    if (i >= Bk*Nn*Dd/4) return;
    int node = i >> 5;
    int c = i & 31;
    int di = dists[node];
    di = di < 0 ? 0 : (di > 9 ? 9 : di);
    float4 dv = __ldg(((const float4*)(dtab + (size_t)di*Dd)) + c);
    float4 nz = ((const float4*)noise)[i];
    float4 h;
    h.x = dv.x + 0.1f*nz.x; h.y = dv.y + 0.1f*nz.y;
    h.z = dv.z + 0.1f*nz.z; h.w = dv.w + 0.1f*nz.w;
    ((float4*)g_h)[i]  = h;
    float4 z = make_float4(0.f, 0.f, 0.f, 0.f);
    ((float4*)g_aggr[0])[i] = z;
    ((float4*)g_aggr[1])[i] = z;
    ((float4*)g_aggr[2])[i] = z;

    __half2* p;
    __half a0, a1;
    a0 = __float2half_rn(h.x); a1 = __float2half_rn(h.y);
    p = (__half2*)g_hhi; p[2*i] = __halves2half2(a0, a1);
    p = (__half2*)g_hlo; p[2*i] = __halves2half2(__float2half_rn(h.x-__half2float(a0)), __float2half_rn(h.y-__half2float(a1)));
    a0 = __float2half_rn(h.z); a1 = __float2half_rn(h.w);
    p = (__half2*)g_hhi; p[2*i+1] = __halves2half2(a0, a1);
    p = (__half2*)g_hlo; p[2*i+1] = __halves2half2(__float2half_rn(h.z-__half2float(a0)), __float2half_rn(h.w-__half2float(a1)));
}

// ---------------- prep: conf fp16 split ----------------
__global__ void prep_aux(const float* __restrict__ conf)
{
    int i = blockIdx.x * blockDim.x + threadIdx.x;
    if (i >= Bk*Ee*Dd/4) return;
    float4 v = ((const float4*)conf)[i];
    int base = i*4;
    __half a0 = __float2half_rn(v.x), a1 = __float2half_rn(v.y);
    __half a2 = __float2half_rn(v.z), a3 = __float2half_rn(v.w);
    *(__half2*)(g_confhi + base)     = __halves2half2(a0, a1);
    *(__half2*)(g_confhi + base + 2) = __halves2half2(a2, a3);
    *(__half2*)(g_conflo + base)     = __halves2half2(__float2half_rn(v.x-__half2float(a0)), __float2half_rn(v.y-__half2float(a1)));
    *(__half2*)(g_conflo + base + 2) = __halves2half2(__float2half_rn(v.z-__half2float(a2)), __float2half_rn(v.w-__half2float(a3)));
}

// ---------------- weight prep ----------------
__global__ void prep_weights(const float* __restrict__ msgW, const float* __restrict__ updW)
{
    int i = blockIdx.x * blockDim.x + threadIdx.x;
    const int MSGTOT = Ll*5*Dd*Dd;
    if (i < MSGTOT) {
        int l = i / (640*128);
        int k = (i / 128) % 640;
        int n = i & 127;
        int ch = k >> 5, kk = k & 31;
        float w = msgW[i];
        __half hi = __float2half_rn(w);
        __half lo = __float2half_rn(w - __half2float(hi));
        size_t o = (((size_t)(l*20 + ch))*128 + n)*32 + kk;
        g_msgWhi[o] = hi; g_msgWlo[o] = lo;
    } else {
        int j = i - MSGTOT;
        if (j < Ll*Dd*Dd) {
            int l = j / (128*128);
            int k = (j / 128) % 128;
            int n = j & 127;
            int ch = k >> 6, kk = k & 63;
            float w = updW[j];
            __half hi = __float2half_rn(w);
            __half lo = __float2half_rn(w - __half2float(hi));
            size_t o = (((size_t)(l*2 + ch))*128 + n)*64 + kk;
            g_updWhi[o] = hi; g_updWlo[o] = lo;
        }
    }
}

// ---------------- table prep (fp32, 4-way ILP) ----------------
__global__ void prep_tbl(const float* __restrict__ dtab,
                         const float* __restrict__ rel_table,
                         const float* __restrict__ msgW)
{
    int i = blockIdx.x * blockDim.x + threadIdx.x;
    if (i >= Ll*(10+Rr)*Dd) return;
    int n = i & 127;
    int row = (i >> 7) % (10+Rr);
    int l = i / ((10+Rr)*Dd);
    const float* Wl = msgW + (size_t)l*640*128;
    const float* vec; const float* w; float* dst;
    if (row < 10) {
        vec = dtab + row*Dd;
        w = Wl + (size_t)2*128*128;
        dst = g_tblD + (l*10 + row)*Dd + n;
    } else {
        vec = rel_table + (size_t)(row-10)*Dd;
        w = Wl + (size_t)3*128*128;
        dst = g_tblR + ((size_t)l*Rr + (row-10))*Dd + n;
    }
    float s0=0.f, s1=0.f, s2=0.f, s3=0.f;
    #pragma unroll
    for (int k = 0; k < 128; k += 4) {
        s0 = fmaf(vec[k],   __ldg(w + (size_t)k*128 + n),       s0);
        s1 = fmaf(vec[k+1], __ldg(w + (size_t)(k+1)*128 + n),   s1);
        s2 = fmaf(vec[k+2], __ldg(w + (size_t)(k+2)*128 + n),   s2);
        s3 = fmaf(vec[k+3], __ldg(w + (size_t)(k+3)*128 + n),   s3);
    }
    *dst = (s0 + s1) + (s2 + s3);
}

// ---------------- edge GEMM (R9 validated): K=384, table epilogue ----------------
__global__ void __launch_bounds__(256, 2)
edge_hmma_kernel(int layer,
                 const int* __restrict__ edge_index,
                 const int* __restrict__ rels,
                 const int* __restrict__ edge_mask,
                 const int* __restrict__ dists,
                 const float* __restrict__ rel_table,
                 const float* __restrict__ bias)
{
    extern __shared__ __half sm[];
    __shared__ int   s_src[128], s_tgt[128], s_rel[128], s_di[128];
    __shared__ float s_em[128], s_bias[128];

    int tid = threadIdx.x, wid = tid >> 5, lane = tid & 31;
    int b  = blockIdx.x >> 7;
    int e0 = (blockIdx.x & 127) << 7;
    size_t bN = (size_t)b * Nn;

    if (tid < 128) {
        int e = e0 + tid;
        int src = edge_index[(size_t)b*2*Ee + e];
        s_src[tid] = src;
        s_tgt[tid] = edge_index[(size_t)b*2*Ee + Ee + e];
        s_rel[tid] = rels[(size_t)b*Ee + e];
        s_em[tid]  = edge_mask[(size_t)b*Ee + e] ? 1.f : 0.f;
        s_bias[tid] = bias[tid];
        int di = dists[bN + src];
        s_di[tid] = di < 0 ? 0 : (di > 9 ? 9 : di);
    }
    __syncthreads();

    uint32_t smb = smem_u32(sm);
    int wm = wid & 3, wn = wid >> 2;
    int g = lane >> 2, t4 = lane & 3;

    float acc[2][8][4];
    #pragma unroll
    for (int i = 0; i < 2; i++)
        #pragma unroll
        for (int j = 0; j < 8; j++)
            #pragma unroll
            for (int q = 0; q < 4; q++) acc[i][j][q] = 0.f;

    auto issue = [&](int c, int st){
        uint32_t sb = smb + (uint32_t)(st*STAGE_H)*2;
        int wc = (c < 4) ? (4 + c) : ((c < 8) ? (12 + c) : (c - 8));
        const __half* wh = g_msgWhi + ((size_t)(layer*20 + wc))*4096;
        const __half* wl = g_msgWlo + ((size_t)(layer*20 + wc))*4096;
        #pragma unroll
        for (int r = 0; r < 2; r++){
            int idx = tid + r*256;
            int n = idx >> 2, f = idx & 3;
            uint32_t d = sb + (uint32_t)(2*TILE_H + n*ESTR + f*8)*2;
            cpa16(d,              wh + n*32 + f*8);
            cpa16(d + TILE_H*2,   wl + n*32 + f*8);
        }
        if (c < 8){
            int koff = (c & 3)*CH;
            #pragma unroll
            for (int r = 0; r < 2; r++){
                int idx = tid + r*256;
                int e = idx >> 2, q = idx & 3;
                size_t rowoff;
                const __half *ph, *pl;
                if (c < 4) { rowoff = (bN + s_src[e])*Dd; ph = g_hhi; pl = g_hlo; }
                else       { rowoff = ((size_t)b*Ee + e0 + e)*Dd; ph = g_confhi; pl = g_conflo; }
                uint32_t d = sb + (uint32_t)(e*ESTR + q*8)*2;
                cpa16(d,            ph + rowoff + koff + q*8);
                cpa16(d + TILE_H*2, pl + rowoff + koff + q*8);
            }
        }
    };
    auto fill0 = [&](int c, int st){
        __half* base = sm + st*STAGE_H;
        int koff = (c - 8)*CH;
        #pragma unroll
        for (int r = 0; r < 2; r++){
            int idx = tid + r*256;
            int e = idx >> 2, q = idx & 3;
            const float* hp = g_h + (bN + s_src[e])*Dd + koff + q*8;
            const float* rp = rel_table + (size_t)s_rel[e]*Dd + koff + q*8;
            float4 h1 = *(const float4*)hp, h2 = *(const float4*)(hp + 4);
            float4 r1 = *(const float4*)rp, r2 = *(const float4*)(rp + 4);
            float pr[8] = {h1.x*r1.x, h1.y*r1.y, h1.z*r1.z, h1.w*r1.w,
                           h2.x*r2.x, h2.y*r2.y, h2.z*r2.z, h2.w*r2.w};
            __half hh[8], ll[8];
            #pragma unroll
            for (int u = 0; u < 8; u++){
                hh[u] = __float2half_rn(pr[u]);
                ll[u] = __float2half_rn(pr[u] - __half2float(hh[u]));
            }
            *(uint4*)(base + e*ESTR + q*8)          = *(uint4*)hh;
            *(uint4*)(base + TILE_H + e*ESTR + q*8) = *(uint4*)ll;
        }
    };

    issue(0, 0); CP_COMMIT();

    for (int c = 0; c < NCH; c++){
        int st = c & 1, nst = st ^ 1;
        if (c + 1 < NCH){
            issue(c + 1, nst);
            if (c + 1 >= 8) fill0(c + 1, nst);
            CP_COMMIT();
            asm volatile("cp.async.wait_group 1;" ::: "memory");
        } else {
            asm volatile("cp.async.wait_group 0;" ::: "memory");
        }
        __syncthreads();

        uint32_t sb = smb + (uint32_t)(st*STAGE_H)*2;
        #pragma unroll
        for (int k16 = 0; k16 < 2; k16++){
            int kb = k16*16;
            uint32_t ah[2][4], al[2][4];
            #pragma unroll
            for (int i = 0; i < 2; i++){
                uint32_t a = sb + (uint32_t)((wm*32 + i*16 + (lane & 15))*ESTR + kb + (lane >> 4)*8)*2;
                LDSM4(ah[i], a);
                LDSM4(al[i], a + TILE_H*2);
            }
            uint32_t bh[2][4], bl[2][4];
            {
                uint32_t bb = sb + (uint32_t)(2*TILE_H + (wn*64 + (lane & 15))*ESTR + kb + (lane >> 4)*8)*2;
                LDSM4(bh[0], bb);
                LDSM4(bl[0], bb + TILE_H*2);
            }
            #pragma unroll
            for (int jp = 0; jp < 4; jp++){
                int cur = jp & 1, nxt = cur ^ 1;
                if (jp < 3){
                    uint32_t bb = sb + (uint32_t)(2*TILE_H + (wn*64 + (jp+1)*16 + (lane & 15))*ESTR + kb + (lane >> 4)*8)*2;
                    LDSM4(bh[nxt], bb);
                    LDSM4(bl[nxt], bb + TILE_H*2);
                }
                MMA_F16(acc[0][jp*2+0], ah[0], bh[cur][0], bh[cur][2]);
                MMA_F16(acc[0][jp*2+1], ah[0], bh[cur][1], bh[cur][3]);
                MMA_F16(acc[1][jp*2+0], ah[1], bh[cur][0], bh[cur][2]);
                MMA_F16(acc[1][jp*2+1], ah[1], bh[cur][1], bh[cur][3]);
                MMA_F16(acc[0][jp*2+0], ah[0], bl[cur][0], bl[cur][2]);
                MMA_F16(acc[0][jp*2+1], ah[0], bl[cur][1], bl[cur][3]);
                MMA_F16(acc[1][jp*2+0], ah[1], bl[cur][0], bl[cur][2]);
                MMA_F16(acc[1][jp*2+1], ah[1], bl[cur][1], bl[cur][3]);
                MMA_F16(acc[0][jp*2+0], al[0], bh[cur][0], bh[cur][2]);
                MMA_F16(acc[0][jp*2+1], al[0], bh[cur][1], bh[cur][3]);
                MMA_F16(acc[1][jp*2+0], al[1], bh[cur][0], bh[cur][2]);
                MMA_F16(acc[1][jp*2+1], al[1], bh[cur][1], bh[cur][3]);
            }
        }
        __syncthreads();
    }

    // epilogue: acc + bias + tblD + tblR -> relu -> masked scatter-add
    float* aggr = g_aggr[layer];
    #pragma unroll
    for (int i = 0; i < 2; i++) {
        #pragma unroll
        for (int half = 0; half < 2; half++) {
            int row = wm*32 + i*16 + g + half*8;
            if (s_em[row] != 0.f) {
                const float* tD = g_tblD + (layer*10 + s_di[row])*Dd;
                const float* tR = g_tblR + ((size_t)layer*Rr + s_rel[row])*Dd;
                float* dst = aggr + (bN + s_tgt[row])*Dd;
                #pragma unroll
                for (int j = 0; j < 8; j++) {
                    int col = wn*64 + j*8 + t4*2;
                    float add0 = s_bias[col]   + __ldg(tD + col)     + __ldg(tR + col);
                    float add1 = s_bias[col+1] + __ldg(tD + col + 1) + __ldg(tR + col + 1);
                    float v0 = acc[i][j][half*2+0] + add0;
                    float v1 = acc[i][j][half*2+1] + add1;
                    if (v0 > 0.f) atomicAdd(dst + col,     v0);
                    if (v1 > 0.f) atomicAdd(dst + col + 1, v1);
                }
            }
        }
    }
}

// ---------------- node update GEMM (validated) + fused h re-split ----------------
__global__ void __launch_bounds__(256, 2)
update_hmma_kernel(int layer, const float* __restrict__ bias)
{
    extern __shared__ __half sm[];
    __half* sAhi = sm;
    __half* sAlo = sAhi + 128*USTR;
    __half* sBhi = sAlo + 128*USTR;
    __half* sBlo = sBhi + 128*USTR;
    __shared__ float s_bias[128];

    int tid = threadIdx.x, wid = tid >> 5, lane = tid & 31;
    size_t r0 = (size_t)blockIdx.x * 128;
    if (tid < 128) s_bias[tid] = bias[tid];
    __syncthreads();

    int wm = wid & 3, wn = wid >> 2;
    int g = lane >> 2, t4 = lane & 3;
    const float* aggr = g_aggr[layer];

    float acc[2][8][4];
    #pragma unroll
    for (int i = 0; i < 2; i++)
        #pragma unroll
        for (int j = 0; j < 8; j++)
            #pragma unroll
            for (int q = 0; q < 4; q++) acc[i][j][q] = 0.f;

    for (int c = 0; c < 2; c++) {
        int koff = c*64;
        #pragma unroll
        for (int it = 0; it < 8; it++) {
            int idx = tid + it*256;
            int row = idx >> 4, q = idx & 15;
            float4 v = *(const float4*)(aggr + (r0 + row)*Dd + koff + q*4);
            __half h0 = __float2half_rn(v.x), h1 = __float2half_rn(v.y);
            __half h2 = __float2half_rn(v.z), h3 = __float2half_rn(v.w);
            int ho = row*USTR + q*4;
            *(__half2*)(sAhi + ho)     = __halves2half2(h0, h1);
            *(__half2*)(sAhi + ho + 2) = __halves2half2(h2, h3);
            *(__half2*)(sAlo + ho)     = __halves2half2(__float2half_rn(v.x-__half2float(h0)), __float2half_rn(v.y-__half2float(h1)));
            *(__half2*)(sAlo + ho + 2) = __halves2half2(__float2half_rn(v.z-__half2float(h2)), __float2half_rn(v.w-__half2float(h3)));
        }
        {
            const uint4* wh = (const uint4*)(g_updWhi + ((size_t)(layer*2 + c))*8192);
            const uint4* wl = (const uint4*)(g_updWlo + ((size_t)(layer*2 + c))*8192);
            #pragma unroll
            for (int it = 0; it < 4; it++) {
                int idx = tid + it*256;
                int n = idx >> 3, q = idx & 7;
                *(uint4*)(sBhi + n*USTR + q*8) = __ldg(wh + idx);
                *(uint4*)(sBlo + n*USTR + q*8) = __ldg(wl + idx);
            }
        }
        __syncthreads();

        #pragma unroll
        for (int k16 = 0; k16 < 4; k16++) {
            int kb = k16*16;
            uint32_t ahi[2][4], alo[2][4];
            #pragma unroll
            for (int i = 0; i < 2; i++) {
                uint32_t a = smem_u32(sAhi + (wm*32 + i*16 + (lane & 15))*USTR + kb + (lane >> 4)*8);
                LDSM4(ahi[i], a);
                LDSM4(alo[i], a + 128*USTR*2);
            }
            #pragma unroll
            for (int jp = 0; jp < 4; jp++) {
                uint32_t bb = smem_u32(sBhi + (wn*64 + jp*16 + (lane & 15))*USTR + kb + (lane >> 4)*8);
                uint32_t bh[4], bl[4];
                LDSM4(bh, bb);
                LDSM4(bl, bb + 128*USTR*2);
                MMA_F16(acc[0][jp*2+0], ahi[0], bh[0], bh[2]);
                MMA_F16(acc[0][jp*2+1], ahi[0], bh[1], bh[3]);
                MMA_F16(acc[1][jp*2+0], ahi[1], bh[0], bh[2]);
                MMA_F16(acc[1][jp*2+1], ahi[1], bh[1], bh[3]);
                MMA_F16(acc[0][jp*2+0], ahi[0], bl[0], bl[2]);
                MMA_F16(acc[0][jp*2+1], ahi[0], bl[1], bl[3]);
                MMA_F16(acc[1][jp*2+0], ahi[1], bl[0], bl[2]);
                MMA_F16(acc[1][jp*2+1], ahi[1], bl[1], bl[3]);
                MMA_F16(acc[0][jp*2+0], alo[0], bh[0], bh[2]);
                MMA_F16(acc[0][jp*2+1], alo[0], bh[1], bh[3]);
                MMA_F16(acc[1][jp*2+0], alo[1], bh[0], bh[2]);
                MMA_F16(acc[1][jp*2+1], alo[1], bh[1], bh[3]);
            }
        }
        __syncthreads();
    }

    #pragma unroll
    for (int i = 0; i < 2; i++) {
        #pragma unroll
        for (int half = 0; half < 2; half++) {
            int row = wm*32 + i*16 + g + half*8;
            size_t gro = (r0 + row)*Dd;
            float* hp = g_h + gro;
            #pragma unroll
            for (int j = 0; j < 8; j++) {
                int col = wn*64 + j*8 + t4*2;
                float v0 = hp[col]     + acc[i][j][half*2+0] + s_bias[col];
                float v1 = hp[col + 1] + acc[i][j][half*2+1] + s_bias[col+1];
                hp[col] = v0; hp[col + 1] = v1;
                __half a0 = __float2half_rn(v0), a1 = __float2half_rn(v1);
                *(__half2*)(g_hhi + gro + col) = __halves2half2(a0, a1);
                *(__half2*)(g_hlo + gro + col) = __halves2half2(
                    __float2half_rn(v0 - __half2float(a0)),
                    __float2half_rn(v1 - __half2float(a1)));
            }
        }
    }
}

// ---------------- attention scores ----------------
__global__ void score_kernel(const float* __restrict__ attW, const float* __restrict__ attb,
                             const int* __restrict__ node_mask,
                             const float* __restrict__ rq)
{
    int gw = blockIdx.x*8 + (threadIdx.x >> 5);
    int lane = threadIdx.x & 31;
    int b = gw / Nn, n = gw % Nn;
    const float* hrow = g_h + (size_t)gw*Dd;
    float s = 0.f;
    #pragma unroll
    for (int i = 0; i < 4; i++) {
        int d = lane + i*32;
        s = fmaf(hrow[d], attW[d], s);
        s = fmaf(rq[b*Dd + d], attW[Dd + d], s);
    }
    #pragma unroll
    for (int o = 16; o; o >>= 1) s += __shfl_xor_sync(0xffffffffu, s, o);
    if (lane == 0) {
        s += attb[0];
        s = (s > 0.f) ? s : 0.01f * s;
        if (!node_mask[(size_t)b*Nn + n]) s = -1e9f;
        g_scores[gw] = s;
    }
}

// ---------------- softmax + top-20 + output: shuffle reductions, 2 bar/pass ----------------
__global__ void __launch_bounds__(1024)
topk_kernel(const int* __restrict__ node_mask, float* __restrict__ out)
{
    __shared__ float ss[Nn];
    __shared__ float rv[32];
    __shared__ int   ri[32];
    __shared__ float s_red;
    __shared__ int   top_i[Mm];
    __shared__ float top_v[Mm];

    int b = blockIdx.x;
    int t = threadIdx.x;
    int w = t >> 5, lane = t & 31;

    for (int i = t; i < Nn; i += 1024) ss[i] = g_scores[(size_t)b*Nn + i];
    __syncthreads();

    // max (shuffle + 32-entry stage)
    float m = -INFINITY;
    for (int i = t; i < Nn; i += 1024) m = fmaxf(m, ss[i]);
    #pragma unroll
    for (int o = 16; o; o >>= 1) m = fmaxf(m, __shfl_xor_sync(0xffffffffu, m, o));
    if (lane == 0) rv[w] = m;
    __syncthreads();
    if (w == 0) {
        float v = rv[lane];
        #pragma unroll
        for (int o = 16; o; o >>= 1) v = fmaxf(v, __shfl_xor_sync(0xffffffffu, v, o));
        if (lane == 0) s_red = v;
    }
    __syncthreads();
    float vmax = s_red;

    // sum exp
    float sum = 0.f;
    for (int i = t; i < Nn; i += 1024) sum += expf(ss[i] - vmax);
    #pragma unroll
    for (int o = 16; o; o >>= 1) sum += __shfl_xor_sync(0xffffffffu, sum, o);
    if (lane == 0) rv[w] = sum;
    __syncthreads();
    if (w == 0) {
        float v = rv[lane];
        #pragma unroll
        for (int o = 16; o; o >>= 1) v += __shfl_xor_sync(0xffffffffu, v, o);
        if (lane == 0) s_red = v;
    }
    __syncthreads();
    float inv = 1.f / s_red;

    // 20 argmax passes: warp bfly + 32-entry cross-warp stage (ties -> lowest index)
    for (int sel = 0; sel < Mm; sel++) {
        float bv = -INFINITY; int bi = Nn;
        for (int i = t; i < Nn; i += 1024) {
            float v = ss[i];
            if (v > bv) { bv = v; bi = i; }
        }
        #pragma unroll
        for (int o = 16; o; o >>= 1) {
            float ov = __shfl_xor_sync(0xffffffffu, bv, o);
            int   oi = __shfl_xor_sync(0xffffffffu, bi, o);
            if (ov > bv || (ov == bv && oi < bi)) { bv = ov; bi = oi; }
        }
        if (lane == 0) { rv[w] = bv; ri[w] = bi; }
        __syncthreads();
        if (w == 0) {
            float v = rv[lane]; int vi = ri[lane];
            #pragma unroll
            for (int o = 16; o; o >>= 1) {
                float ov = __shfl_xor_sync(0xffffffffu, v, o);
                int   oi = __shfl_xor_sync(0xffffffffu, vi, o);
                if (ov > v || (ov == v && oi < vi)) { v = ov; vi = oi; }
            }
            if (lane == 0) { top_i[sel] = vi; top_v[sel] = v; ss[vi] = -INFINITY; }
        }
        __syncthreads();
    }

    for (int i = t; i < Mm*Dd; i += 1024) {
        int sel = i / Dd, d = i % Dd;
        int idx = top_i[sel];
        float alpha = expf(top_v[sel] - vmax) * inv;
        float mk = node_mask[(size_t)b*Nn + idx] ? 1.f : 0.f;
        float hv = g_h[((size_t)b*Nn + idx)*Dd + d] * mk;
        out[((size_t)b*Mm + sel)*Dd + d] = hv * alpha;
    }
    float m0 = node_mask[(size_t)b*Nn] ? 1.f : 0.f;
    for (int d = t; d < Dd; d += 1024)
        out[(size_t)Bk*Mm*Dd + (size_t)b*Dd + d] = g_h[((size_t)b*Nn)*Dd + d] * m0;
}

// ---------------- launch ----------------
extern "C" void kernel_launch(void* const* d_in, const int* in_sizes, int n_in,
                              void* d_out, int out_size)
{
    (void)in_sizes; (void)n_in; (void)out_size;
    const int*   dists      = (const int*)d_in[0];
    const int*   edge_index = (const int*)d_in[1];
    const int*   rels       = (const int*)d_in[2];
    const int*   node_mask  = (const int*)d_in[3];
    const int*   edge_mask  = (const int*)d_in[4];
    const float* rq         = (const float*)d_in[5];
    const float* conf       = (const float*)d_in[6];
    const float* noise      = (const float*)d_in[7];
    const float* dist_table = (const float*)d_in[8];
    const float* rel_table  = (const float*)d_in[9];
    const float* msg_W      = (const float*)d_in[10];
    const float* msg_b      = (const float*)d_in[11];
    const float* upd_W      = (const float*)d_in[12];
    const float* upd_b      = (const float*)d_in[13];
    const float* att_W      = (const float*)d_in[14];
    const float* att_b      = (const float*)d_in[15];
    float* out = (float*)d_out;

    cudaFuncSetAttribute(edge_hmma_kernel, cudaFuncAttributeMaxDynamicSharedMemorySize, ESMEM);
    cudaFuncSetAttribute(update_hmma_kernel, cudaFuncAttributeMaxDynamicSharedMemorySize, (int)USMEM);

    int total4 = Bk*Nn*Dd/4;
    prep_kernel<<<(total4 + 255)/256, 256>>>(dists, noise, dist_table);
    prep_aux<<<(Bk*Ee*Dd/4 + 255)/256, 256>>>(conf);
    prep_weights<<<(Ll*5*Dd*Dd + Ll*Dd*Dd + 255)/256, 256>>>(msg_W, upd_W);
    prep_tbl<<<(Ll*(10+Rr)*Dd + 255)/256, 256>>>(dist_table, rel_table, msg_W);

    for (int l = 0; l < Ll; l++) {
        edge_hmma_kernel<<<Bk*(Ee/128), 256, ESMEM>>>(
            l, edge_index, rels, edge_mask, dists, rel_table, msg_b + (size_t)l*Dd);
        update_hmma_kernel<<<Bk*Nn/128, 256, USMEM>>>(l, upd_b + (size_t)l*Dd);
    }

    score_kernel<<<Bk*Nn/8, 256>>>(att_W, att_b, node_mask, rq);
    topk_kernel<<<Bk, 1024>>>(node_mask, out);
}